// round 7
// baseline (speedup 1.0000x reference)
#include <cuda_runtime.h>
#include <cuda_bf16.h>
#include <math.h>
#include <stdint.h>

#define B_  8
#define T_  1024
#define D_  768
#define H_  12
#define HD_ 64
#define BH_ (B_*H_)   /* 96 */
#define N_  (B_*T_)   /* 8192 */
#define WSZ_ ((size_t)D_*D_)

// ---- scratch (static device globals; no allocation) ----
__device__ __nv_bfloat16 g_xh[N_*D_];       // x hi bf16
__device__ __nv_bfloat16 g_xl[N_*D_];       // x lo bf16
__device__ __nv_bfloat16 g_wth[4][D_*D_];   // W^T hi (q,k,v,o), [n][k]
__device__ __nv_bfloat16 g_wtl[4][D_*D_];   // W^T lo
__device__ uint32_t g_q[BH_*T_*HD_];        // tf32, head layout
__device__ uint32_t g_k[BH_*T_*HD_];
__device__ uint32_t g_v[BH_*T_*HD_];
__device__ __nv_bfloat16 g_oh[N_*D_];       // attn out hi bf16, row-major
__device__ __nv_bfloat16 g_ol[N_*D_];       // attn out lo
__device__ float    g_ga1[BH_*T_];
__device__ float    g_wg2[HD_*2];
__device__ float    g_bg2[2];

// ---- helpers ----
__device__ __forceinline__ uint32_t f2tf(float f) {
    uint32_t u;
    asm("cvt.rna.tf32.f32 %0, %1;" : "=r"(u) : "f"(f));
    return u;
}
__device__ __forceinline__ void mma_tf32(float* d, const uint32_t* a, const uint32_t* b) {
    asm volatile(
        "mma.sync.aligned.m16n8k8.row.col.f32.tf32.tf32.f32 "
        "{%0,%1,%2,%3}, {%4,%5,%6,%7}, {%8,%9}, {%0,%1,%2,%3};\n"
        : "+f"(d[0]), "+f"(d[1]), "+f"(d[2]), "+f"(d[3])
        : "r"(a[0]), "r"(a[1]), "r"(a[2]), "r"(a[3]), "r"(b[0]), "r"(b[1]));
}
__device__ __forceinline__ void mma_bf16(float* d, const uint32_t* a, const uint32_t* b) {
    asm volatile(
        "mma.sync.aligned.m16n8k16.row.col.f32.bf16.bf16.f32 "
        "{%0,%1,%2,%3}, {%4,%5,%6,%7}, {%8,%9}, {%0,%1,%2,%3};\n"
        : "+f"(d[0]), "+f"(d[1]), "+f"(d[2]), "+f"(d[3])
        : "r"(a[0]), "r"(a[1]), "r"(a[2]), "r"(a[3]), "r"(b[0]), "r"(b[1]));
}
#define LDSM_X4(r, a) \
    asm volatile("ldmatrix.sync.aligned.m8n8.x4.shared.b16 {%0,%1,%2,%3}, [%4];" \
        : "=r"((r)[0]), "=r"((r)[1]), "=r"((r)[2]), "=r"((r)[3]) : "r"(a))

__device__ __forceinline__ uint32_t saddr(const void* p) {
    return (uint32_t)__cvta_generic_to_shared(p);
}
__device__ __forceinline__ void cp16(uint32_t s, const void* g) {
    asm volatile("cp.async.cg.shared.global [%0], [%1], 16;\n" :: "r"(s), "l"(g));
}
#define CP_COMMIT() asm volatile("cp.async.commit_group;\n")
#define CP_WAIT1()  asm volatile("cp.async.wait_group 1;\n")
#define CP_WAIT0()  asm volatile("cp.async.wait_group 0;\n")

__device__ __forceinline__ void bfsplit(float f, __nv_bfloat16& h, __nv_bfloat16& l) {
    h = __float2bfloat16(f);
    l = __float2bfloat16(f - __bfloat162float(h));
}

// ============================================================
// conv_x: x -> bf16 hi/lo (+ block 0 computes Wg row-sums)
// ============================================================
__global__ void conv_x(const float4* __restrict__ in,
                       __nv_bfloat16* __restrict__ xh, __nv_bfloat16* __restrict__ xl,
                       int n4, const float* __restrict__ Wg, const float* __restrict__ bg)
{
    int i = blockIdx.x * blockDim.x + threadIdx.x;
    if (blockIdx.x == 0 && threadIdx.x < 64) {
        int d = threadIdx.x;
        const float* wg = Wg + d * 8;
        g_wg2[d * 2 + 0] = wg[0] + wg[1] + wg[2] + wg[3];
        g_wg2[d * 2 + 1] = wg[4] + wg[5] + wg[6] + wg[7];
        if (d == 0) {
            g_bg2[0] = bg[0] + bg[1] + bg[2] + bg[3];
            g_bg2[1] = bg[4] + bg[5] + bg[6] + bg[7];
        }
    }
    if (i >= n4) return;
    float4 v = in[i];
    __nv_bfloat16 h0,h1,h2,h3,l0,l1,l2,l3;
    bfsplit(v.x,h0,l0); bfsplit(v.y,h1,l1); bfsplit(v.z,h2,l2); bfsplit(v.w,h3,l3);
    __nv_bfloat162* ph = (__nv_bfloat162*)(xh + (size_t)i*4);
    __nv_bfloat162* pl = (__nv_bfloat162*)(xl + (size_t)i*4);
    ph[0] = {h0,h1}; ph[1] = {h2,h3};
    pl[0] = {l0,l1}; pl[1] = {l2,l3};
}

// ============================================================
// conv_wT: W -> W^T bf16 hi/lo (4 matrices via grid.z)
// ============================================================
__global__ void conv_wT(const float* __restrict__ W0, const float* __restrict__ W1,
                        const float* __restrict__ W2, const float* __restrict__ W3,
                        __nv_bfloat16* __restrict__ th, __nv_bfloat16* __restrict__ tl)
{
    __shared__ float tile[32][33];
    const int z = blockIdx.z;
    const float* W = (z==0)?W0:(z==1)?W1:(z==2)?W2:W3;
    __nv_bfloat16* dh = th + (size_t)z * WSZ_;
    __nv_bfloat16* dl = tl + (size_t)z * WSZ_;
    int n0 = blockIdx.x * 32, k0 = blockIdx.y * 32;
    int tx = threadIdx.x, ty = threadIdx.y;
    tile[ty][tx] = W[(size_t)(k0 + ty) * D_ + n0 + tx];
    __syncthreads();
    float f = tile[tx][ty];
    __nv_bfloat16 h, l;
    bfsplit(f, h, l);
    size_t o = (size_t)(n0 + ty) * D_ + k0 + tx;
    dh[o] = h; dl[o] = l;
}

// ============================================================
// Gates: warp per (bh,t) using precomputed wg2.
// ============================================================
__global__ __launch_bounds__(256)
void gates_kernel(const float* __restrict__ x, const float* __restrict__ grep_a,
                  float* __restrict__ ga1)
{
    int w    = blockIdx.x * 8 + (threadIdx.x >> 5);
    int lane = threadIdx.x & 31;
    int bh = w >> 10, t = w & 1023;
    int b = bh / H_, h = bh % H_;
    const float* xp = x + ((size_t)b * T_ + t) * D_ + h * HD_;

    float s0 = 0.f, s1 = 0.f;
#pragma unroll
    for (int d = lane; d < HD_; d += 32) {
        float xv = xp[d];
        s0 += xv * g_wg2[d * 2 + 0];
        s1 += xv * g_wg2[d * 2 + 1];
    }
#pragma unroll
    for (int off = 16; off > 0; off >>= 1) {
        s0 += __shfl_xor_sync(0xffffffffu, s0, off);
        s1 += __shfl_xor_sync(0xffffffffu, s1, off);
    }
    if (lane == 0) {
        s0 += g_bg2[0];
        s1 += g_bg2[1];
        float ga = 1.f / (1.f + expf(-s0));
        float gb = 1.f / (1.f + expf(-s1));
        ga1[w] = ga * (gb * grep_a[h] - 1.f) + 2.f;
    }
}

// ============================================================
// bf16 3-term GEMM (Ah.Bh + Ah.Bl + Al.Bh) with ldmatrix.
// A hi/lo [8192][768] bf16 row-major; B = W^T hi/lo [768][768] bf16 [n][k].
// BM=128 BN=128 BK=32, 2-stage cp.async ring, 256 thr (8 warps 2m x 4n).
// MODE 0: out tf32 u32 head-layout (+bias), z selects q/k/v.
// MODE 1: out fp32 row-major (+bias).
// ============================================================
#define OB_STAGE 40960
template<int MODE>
__global__ __launch_bounds__(256, 2)
void gemm3t(const __nv_bfloat16* __restrict__ Ah, const __nv_bfloat16* __restrict__ Al,
            const __nv_bfloat16* __restrict__ Wth, const __nv_bfloat16* __restrict__ Wtl,
            const float* __restrict__ b0, const float* __restrict__ b1,
            const float* __restrict__ b2,
            uint32_t* o0, uint32_t* o1, uint32_t* o2, float* oF)
{
    extern __shared__ char smo[];
    const int tid = threadIdx.x;
    const int z = blockIdx.z;
    const __nv_bfloat16* Bh = Wth + (size_t)z * WSZ_;
    const __nv_bfloat16* Bl = Wtl + (size_t)z * WSZ_;
    const float* bias = (z == 0) ? b0 : (z == 1) ? b1 : b2;
    uint32_t* outU    = (z == 0) ? o0 : (z == 1) ? o1 : o2;

    const int w = tid >> 5, lane = tid & 31, g = lane >> 2, q4 = lane & 3;
    const int wm = (w & 1) * 64, wn = (w >> 1) * 32;
    const int row0 = blockIdx.x * 128, col0 = blockIdx.y * 128;

    float acc[4][4][4];
#pragma unroll
    for (int i = 0; i < 4; i++)
#pragma unroll
        for (int f = 0; f < 4; f++)
#pragma unroll
            for (int e = 0; e < 4; e++) acc[i][f][e] = 0.f;

    const int lrow = lane & 15;
    const int lchk = (lane >> 4) * 16;

#define G3_STAGE_LOAD(s, k0) do {                                              \
    char* base_ = smo + (s) * OB_STAGE;                                        \
    _Pragma("unroll")                                                          \
    for (int i = 0; i < 2; i++) {                                              \
        int idx = tid + i * 256;                                               \
        int r = idx >> 2, ch = idx & 3;                                        \
        uint32_t so = saddr(base_ + r * 80 + ch * 16);                         \
        cp16(so,         Ah + (size_t)(row0 + r) * D_ + (k0) + ch * 8);        \
        cp16(so + 10240, Al + (size_t)(row0 + r) * D_ + (k0) + ch * 8);        \
        cp16(so + 20480, Bh + (size_t)(col0 + r) * D_ + (k0) + ch * 8);        \
        cp16(so + 30720, Bl + (size_t)(col0 + r) * D_ + (k0) + ch * 8);        \
    } } while (0)

    G3_STAGE_LOAD(0, 0);  CP_COMMIT();
    G3_STAGE_LOAD(1, 32); CP_COMMIT();

    for (int kb = 0; kb < 24; kb++) {
        if (kb + 1 < 24) CP_WAIT1(); else CP_WAIT0();
        __syncthreads();
        char* base = smo + (kb & 1) * OB_STAGE;
#pragma unroll
        for (int ks = 0; ks < 2; ks++) {
            uint32_t ah[4][4], al[4][4];
#pragma unroll
            for (int i = 0; i < 4; i++) {
                uint32_t a = saddr(base + (wm + 16 * i + lrow) * 80 + ks * 32 + lchk);
                LDSM_X4(ah[i], a);
                LDSM_X4(al[i], a + 10240);
            }
            uint32_t bh4[2][4], bl4[2][4];
#pragma unroll
            for (int j = 0; j < 2; j++) {
                uint32_t a = saddr(base + 20480 + (wn + 16 * j + lrow) * 80 + ks * 32 + lchk);
                LDSM_X4(bh4[j], a);
                LDSM_X4(bl4[j], a + 10240);
            }
#pragma unroll
            for (int i = 0; i < 4; i++)
#pragma unroll
                for (int f = 0; f < 4; f++) {
                    uint32_t bhf[2] = { bh4[f >> 1][f & 1], bh4[f >> 1][(f & 1) + 2] };
                    uint32_t blf[2] = { bl4[f >> 1][f & 1], bl4[f >> 1][(f & 1) + 2] };
                    mma_bf16(acc[i][f], ah[i], bhf);
                    mma_bf16(acc[i][f], ah[i], blf);
                    mma_bf16(acc[i][f], al[i], bhf);
                }
        }
        __syncthreads();
        if (kb + 2 < 24) { G3_STAGE_LOAD(kb & 1, (kb + 2) * 32); CP_COMMIT(); }
    }

#pragma unroll
    for (int i = 0; i < 4; i++)
#pragma unroll
        for (int f = 0; f < 4; f++) {
            int col = col0 + wn + 8 * f + 2 * q4;
            float bb0 = bias[col], bb1 = bias[col + 1];
#pragma unroll
            for (int half = 0; half < 2; half++) {
                int row = row0 + wm + 16 * i + g + 8 * half;
                float v0 = acc[i][f][2 * half + 0] + bb0;
                float v1 = acc[i][f][2 * half + 1] + bb1;
                if (MODE == 0) {
                    int bb = row >> 10, tt = row & 1023;
                    int hh = col >> 6, hd = col & 63;
                    uint2 u; u.x = f2tf(v0); u.y = f2tf(v1);
                    *(uint2*)(outU + ((size_t)(bb * H_ + hh) * T_ + tt) * HD_ + hd) = u;
                } else {
                    float2 v; v.x = v0; v.y = v1;
                    *(float2*)(oF + (size_t)row * D_ + col) = v;
                }
            }
        }
}

// ============================================================
// Flash attention: paired-tile softmax over 64 k per pass.
// q-tile 128, 2x 32-k stages, 8 warps. q/k/v tf32. bf16 hi/lo epilogue.
// ============================================================
#define ATT_STAGE 8576
#define C_SM (0.125f * 1.44269504088896340736f)   /* 0.125*log2(e) */
__global__ __launch_bounds__(256, 2)
void attn_kernel(const float* __restrict__ rel_bias,
                 const float* __restrict__ attn_mask)
{
    extern __shared__ float smf[];
    uint32_t* Pp = (uint32_t*)(smf + 2 * ATT_STAGE);   // [128][36]
    float*    Ms = smf + 2 * ATT_STAGE + 4608;         // [1024]

    const int tid  = threadIdx.x;
    const int w    = tid >> 5;
    const int lane = tid & 31;
    const int g    = lane >> 2;
    const int q4   = lane & 3;
    const int qb   = 16 * w;
    const int q0   = blockIdx.x * 128;
    const int bh   = blockIdx.y;
    const int b    = bh / H_, h = bh % H_;

    const uint32_t* qptr = g_q + (size_t)bh * T_ * HD_;
    const uint32_t* kptr = g_k + (size_t)bh * T_ * HD_;
    const uint32_t* vptr = g_v + (size_t)bh * T_ * HD_;

    const int r0 = qb + g;
    const int r1 = qb + g + 8;

#define ATT_STAGE_LOAD(s, k0) do {                                             \
    uint32_t* Ks_ = (uint32_t*)(smf + (s) * ATT_STAGE);                        \
    uint32_t* Vs_ = Ks_ + 2176;                                                \
    float*    RB_ = smf + (s) * ATT_STAGE + 4352;                              \
    _Pragma("unroll")                                                          \
    for (int i = 0; i < 2; i++) {                                              \
        int idx = tid + i * 256;                                               \
        int kk = idx >> 4, d4 = (idx & 15) * 4;                                \
        cp16(saddr(&Ks_[kk * 68 + d4]), kptr + (size_t)((k0) + kk) * HD_ + d4);\
        cp16(saddr(&Vs_[kk * 68 + d4]), vptr + (size_t)((k0) + kk) * HD_ + d4);\
    }                                                                          \
    const float* rbp_ = rel_bias + ((size_t)bh * T_ + (k0)) * T_ + q0;         \
    _Pragma("unroll")                                                          \
    for (int i = 0; i < 4; i++) {                                              \
        int idx = tid + i * 256;                                               \
        int kk = idx >> 5, qq = (idx & 31) * 4;                                \
        cp16(saddr(&RB_[kk * 132 + qq]), rbp_ + (size_t)kk * T_ + qq);         \
    } } while (0)

    // QK over one stage -> 4x4 sacc (raw, already *C_SM)
#define ATT_QK(stg, k0, sacc) do {                                             \
    const uint32_t* Ks = (const uint32_t*)(smf + (stg) * ATT_STAGE);           \
    const float*    RB = smf + (stg) * ATT_STAGE + 4352;                       \
    _Pragma("unroll")                                                          \
    for (int f = 0; f < 4; f++) {                                              \
        int c0 = 8 * f + 2 * q4;                                               \
        sacc[f][0] = 8.f * fmaf(ga0,  RB[c0 * 132 + r0],       Ms[(k0) + c0]); \
        sacc[f][1] = 8.f * fmaf(ga0,  RB[(c0 + 1) * 132 + r0], Ms[(k0) + c0 + 1]); \
        sacc[f][2] = 8.f * fmaf(ga1v, RB[c0 * 132 + r1],       Ms[(k0) + c0]); \
        sacc[f][3] = 8.f * fmaf(ga1v, RB[(c0 + 1) * 132 + r1], Ms[(k0) + c0 + 1]); \
    }                                                                          \
    _Pragma("unroll")                                                          \
    for (int s = 0; s < 8; s++) {                                              \
        uint32_t bf[4][2];                                                     \
        _Pragma("unroll")                                                      \
        for (int f = 0; f < 4; f++) {                                          \
            bf[f][0] = Ks[(8 * f + g) * 68 + q4 + 8 * s];                      \
            bf[f][1] = Ks[(8 * f + g) * 68 + q4 + 4 + 8 * s];                  \
        }                                                                      \
        _Pragma("unroll")                                                      \
        for (int f = 0; f < 4; f++) mma_tf32(sacc[f], qf[s], bf[f]);           \
    }                                                                          \
    _Pragma("unroll")                                                          \
    for (int f = 0; f < 4; f++)                                                \
        _Pragma("unroll")                                                      \
        for (int e = 0; e < 4; e++) sacc[f][e] *= C_SM;                        \
    } while (0)

    // P store + PV over one stage
#define ATT_PV(stg, sacc) do {                                                 \
    const uint32_t* Vs = (const uint32_t*)(smf + (stg) * ATT_STAGE) + 2176;    \
    _Pragma("unroll")                                                          \
    for (int f = 0; f < 4; f++) {                                              \
        int c0 = 8 * f + 2 * q4;                                               \
        Pp[r0 * 36 + c0]     = f2tf(sacc[f][0]);                               \
        Pp[r0 * 36 + c0 + 1] = f2tf(sacc[f][1]);                               \
        Pp[r1 * 36 + c0]     = f2tf(sacc[f][2]);                               \
        Pp[r1 * 36 + c0 + 1] = f2tf(sacc[f][3]);                               \
    }                                                                          \
    __syncwarp();                                                              \
    _Pragma("unroll")                                                          \
    for (int s = 0; s < 4; s++) {                                              \
        uint32_t pa[4];                                                        \
        pa[0] = Pp[r0 * 36 + q4 + 8 * s];                                      \
        pa[1] = Pp[r1 * 36 + q4 + 8 * s];                                      \
        pa[2] = Pp[r0 * 36 + q4 + 4 + 8 * s];                                  \
        pa[3] = Pp[r1 * 36 + q4 + 4 + 8 * s];                                  \
        _Pragma("unroll")                                                      \
        for (int f = 0; f < 8; f++) {                                          \
            uint32_t vb[2];                                                    \
            vb[0] = Vs[(8 * s + q4) * 68 + 8 * f + g];                         \
            vb[1] = Vs[(8 * s + q4 + 4) * 68 + 8 * f + g];                     \
            mma_tf32(oacc[f], pa, vb);                                         \
        }                                                                      \
    } } while (0)

    // prologue
    ATT_STAGE_LOAD(0, 0);
    cp16(saddr(&Ms[tid * 4]), attn_mask + (size_t)b * T_ + tid * 4);
    CP_COMMIT();
    ATT_STAGE_LOAD(1, 32);
    CP_COMMIT();

    uint32_t qf[8][4];
    {
        const uint32_t* qa = qptr + (size_t)(q0 + r0) * HD_;
        const uint32_t* qc = qptr + (size_t)(q0 + r1) * HD_;
#pragma unroll
        for (int s = 0; s < 8; s++) {
            qf[s][0] = qa[q4 + 8 * s];
            qf[s][1] = qc[q4 + 8 * s];
            qf[s][2] = qa[q4 + 4 + 8 * s];
            qf[s][3] = qc[q4 + 4 + 8 * s];
        }
    }
    const float ga0  = g_ga1[(size_t)bh * T_ + q0 + r0];
    const float ga1v = g_ga1[(size_t)bh * T_ + q0 + r1];

    float m_[2] = {-INFINITY, -INFINITY};
    float l_[2] = {0.f, 0.f};
    float oacc[8][4];
#pragma unroll
    for (int f = 0; f < 8; f++)
#pragma unroll
        for (int e = 0; e < 4; e++) oacc[f][e] = 0.f;

    for (int p = 0; p < 16; p++) {
        CP_WAIT0();
        __syncthreads();
        const int k0 = p * 64;

        float sacc0[4][4], sacc1[4][4];
        ATT_QK(0, k0, sacc0);
        ATT_QK(1, k0 + 32, sacc1);

        // ---- combined softmax over 64 cols ----
        float mt0 = sacc0[0][0], mt1 = sacc0[0][2];
#pragma unroll
        for (int f = 0; f < 4; f++) {
            mt0 = fmaxf(mt0, fmaxf(fmaxf(sacc0[f][0], sacc0[f][1]),
                                   fmaxf(sacc1[f][0], sacc1[f][1])));
            mt1 = fmaxf(mt1, fmaxf(fmaxf(sacc0[f][2], sacc0[f][3]),
                                   fmaxf(sacc1[f][2], sacc1[f][3])));
        }
        mt0 = fmaxf(mt0, __shfl_xor_sync(0xffffffffu, mt0, 1));
        mt0 = fmaxf(mt0, __shfl_xor_sync(0xffffffffu, mt0, 2));
        mt1 = fmaxf(mt1, __shfl_xor_sync(0xffffffffu, mt1, 1));
        mt1 = fmaxf(mt1, __shfl_xor_sync(0xffffffffu, mt1, 2));

        float mn0 = fmaxf(m_[0], mt0), mn1 = fmaxf(m_[1], mt1);
        float al0 = exp2f(m_[0] - mn0), al1 = exp2f(m_[1] - mn1);
        m_[0] = mn0; m_[1] = mn1;

        float ls0 = 0.f, ls1 = 0.f;
#pragma unroll
        for (int f = 0; f < 4; f++) {
            sacc0[f][0] = exp2f(sacc0[f][0] - mn0);
            sacc0[f][1] = exp2f(sacc0[f][1] - mn0);
            sacc0[f][2] = exp2f(sacc0[f][2] - mn1);
            sacc0[f][3] = exp2f(sacc0[f][3] - mn1);
            sacc1[f][0] = exp2f(sacc1[f][0] - mn0);
            sacc1[f][1] = exp2f(sacc1[f][1] - mn0);
            sacc1[f][2] = exp2f(sacc1[f][2] - mn1);
            sacc1[f][3] = exp2f(sacc1[f][3] - mn1);
            ls0 += sacc0[f][0] + sacc0[f][1] + sacc1[f][0] + sacc1[f][1];
            ls1 += sacc0[f][2] + sacc0[f][3] + sacc1[f][2] + sacc1[f][3];
        }
        ls0 += __shfl_xor_sync(0xffffffffu, ls0, 1);
        ls0 += __shfl_xor_sync(0xffffffffu, ls0, 2);
        ls1 += __shfl_xor_sync(0xffffffffu, ls1, 1);
        ls1 += __shfl_xor_sync(0xffffffffu, ls1, 2);
        l_[0] = l_[0] * al0 + ls0;
        l_[1] = l_[1] * al1 + ls1;
#pragma unroll
        for (int f = 0; f < 8; f++) {
            oacc[f][0] *= al0; oacc[f][1] *= al0;
            oacc[f][2] *= al1; oacc[f][3] *= al1;
        }

        // ---- PV tile 0, recycle stage 0, PV tile 1, recycle stage 1 ----
        ATT_PV(0, sacc0);
        __syncthreads();                    // all warps done with stage 0 + Pp
        if (p < 15) { ATT_STAGE_LOAD(0, k0 + 64); CP_COMMIT(); }
        ATT_PV(1, sacc1);
        __syncthreads();                    // all warps done with stage 1
        if (p < 15) { ATT_STAGE_LOAD(1, k0 + 96); CP_COMMIT(); }
    }

    // ---- finalize: O /= l ; write bf16 hi/lo row-major [b*t][h*64+hd] ----
    float inv0 = 1.f / l_[0], inv1 = 1.f / l_[1];
#pragma unroll
    for (int f = 0; f < 8; f++) {
        int c = 8 * f + 2 * q4;
        size_t i0 = ((size_t)b * T_ + q0 + r0) * D_ + h * HD_ + c;
        size_t i1 = ((size_t)b * T_ + q0 + r1) * D_ + h * HD_ + c;
        float v00 = oacc[f][0] * inv0, v01 = oacc[f][1] * inv0;
        float v10 = oacc[f][2] * inv1, v11 = oacc[f][3] * inv1;
        __nv_bfloat16 h00,l00,h01,l01,h10,l10,h11,l11;
        bfsplit(v00,h00,l00); bfsplit(v01,h01,l01);
        bfsplit(v10,h10,l10); bfsplit(v11,h11,l11);
        *(__nv_bfloat162*)(g_oh + i0) = {h00, h01};
        *(__nv_bfloat162*)(g_ol + i0) = {l00, l01};
        *(__nv_bfloat162*)(g_oh + i1) = {h10, h11};
        *(__nv_bfloat162*)(g_ol + i1) = {l10, l11};
    }
}

// ============================================================
extern "C" void kernel_launch(void* const* d_in, const int* in_sizes, int n_in,
                              void* d_out, int out_size)
{
    const float* x         = (const float*)d_in[0];
    const float* attn_mask = (const float*)d_in[1];
    const float* rel_bias  = (const float*)d_in[2];
    const float* Wq = (const float*)d_in[3];
    const float* bq = (const float*)d_in[4];
    const float* Wk = (const float*)d_in[5];
    const float* bk = (const float*)d_in[6];
    const float* Wv = (const float*)d_in[7];
    const float* bv = (const float*)d_in[8];
    const float* Wo = (const float*)d_in[9];
    const float* bo = (const float*)d_in[10];
    const float* Wg = (const float*)d_in[11];
    const float* bg = (const float*)d_in[12];
    const float* grep_a = (const float*)d_in[13];
    float* out = (float*)d_out;

    __nv_bfloat16 *xh, *xl, *wth, *wtl, *oh, *ol;
    uint32_t *q, *k, *v;
    float *ga1;
    cudaGetSymbolAddress((void**)&xh,  g_xh);
    cudaGetSymbolAddress((void**)&xl,  g_xl);
    cudaGetSymbolAddress((void**)&wth, g_wth);
    cudaGetSymbolAddress((void**)&wtl, g_wtl);
    cudaGetSymbolAddress((void**)&q,   g_q);
    cudaGetSymbolAddress((void**)&k,   g_k);
    cudaGetSymbolAddress((void**)&v,   g_v);
    cudaGetSymbolAddress((void**)&oh,  g_oh);
    cudaGetSymbolAddress((void**)&ol,  g_ol);
    cudaGetSymbolAddress((void**)&ga1, g_ga1);

    cudaFuncSetAttribute(gemm3t<0>,   cudaFuncAttributeMaxDynamicSharedMemorySize, OB_STAGE * 2);
    cudaFuncSetAttribute(gemm3t<1>,   cudaFuncAttributeMaxDynamicSharedMemorySize, OB_STAGE * 2);
    cudaFuncSetAttribute(attn_kernel, cudaFuncAttributeMaxDynamicSharedMemorySize, 91136);

    const int nx4 = N_ * D_ / 4;
    conv_x<<<(nx4 + 255) / 256, 256>>>((const float4*)x, xh, xl, nx4, Wg, bg);        // 0
    conv_wT<<<dim3(24, 24, 4), dim3(32, 32)>>>(Wq, Wk, Wv, Wo, wth, wtl);             // 1
    gates_kernel<<<BH_ * T_ / 8, 256>>>(x, grep_a, ga1);                              // 2
    gemm3t<0><<<dim3(64, 6, 3), 256, OB_STAGE * 2>>>(                                 // 3
        xh, xl, wth, wtl, bq, bk, bv, q, k, v, (float*)0);
    attn_kernel<<<dim3(T_ / 128, BH_), 256, 91136>>>(rel_bias, attn_mask);            // 4
    gemm3t<1><<<dim3(64, 6), 256, OB_STAGE * 2>>>(                                    // 5
        oh, ol, wth + 3 * WSZ_, wtl + 3 * WSZ_, bo, bo, bo,
        (uint32_t*)0, (uint32_t*)0, (uint32_t*)0, out);
}

// round 8
// speedup vs baseline: 1.0933x; 1.0933x over previous
#include <cuda_runtime.h>
#include <cuda_bf16.h>
#include <math.h>
#include <stdint.h>

#define B_  8
#define T_  1024
#define D_  768
#define H_  12
#define HD_ 64
#define BH_ (B_*H_)   /* 96 */
#define N_  (B_*T_)   /* 8192 */
#define WSZ_ ((size_t)D_*D_)

// ---- scratch (static device globals; no allocation) ----
__device__ uint32_t g_xhi[N_*D_];          // x tf32
__device__ uint32_t g_wqh[D_*D_];          // Wq tf32
__device__ uint32_t g_wkh[D_*D_];
__device__ uint32_t g_wvh[D_*D_];
__device__ __nv_bfloat16 g_woth[D_*D_];    // Wo^T bf16 hi [n][k]
__device__ __nv_bfloat16 g_wotl[D_*D_];    // Wo^T bf16 lo
__device__ uint32_t g_q[BH_*T_*HD_];       // tf32, head layout, perm4 in hd
__device__ uint32_t g_k[BH_*T_*HD_];       // perm4
__device__ uint32_t g_v[BH_*T_*HD_];       // perm8
__device__ __nv_bfloat16 g_oh[N_*D_];      // attn out hi bf16, row-major
__device__ __nv_bfloat16 g_ol[N_*D_];      // attn out lo
__device__ float    g_ga1[BH_*T_];
__device__ float    g_wg2[HD_*2];
__device__ float    g_bg2[2];

// ---- helpers ----
__device__ __forceinline__ uint32_t f2tf(float f) {
    uint32_t u;
    asm("cvt.rna.tf32.f32 %0, %1;" : "=r"(u) : "f"(f));
    return u;
}
__device__ __forceinline__ void mma_tf32(float* d, const uint32_t* a, const uint32_t* b) {
    asm volatile(
        "mma.sync.aligned.m16n8k8.row.col.f32.tf32.tf32.f32 "
        "{%0,%1,%2,%3}, {%4,%5,%6,%7}, {%8,%9}, {%0,%1,%2,%3};\n"
        : "+f"(d[0]), "+f"(d[1]), "+f"(d[2]), "+f"(d[3])
        : "r"(a[0]), "r"(a[1]), "r"(a[2]), "r"(a[3]), "r"(b[0]), "r"(b[1]));
}
__device__ __forceinline__ void mma_bf16(float* d, const uint32_t* a, const uint32_t* b) {
    asm volatile(
        "mma.sync.aligned.m16n8k16.row.col.f32.bf16.bf16.f32 "
        "{%0,%1,%2,%3}, {%4,%5,%6,%7}, {%8,%9}, {%0,%1,%2,%3};\n"
        : "+f"(d[0]), "+f"(d[1]), "+f"(d[2]), "+f"(d[3])
        : "r"(a[0]), "r"(a[1]), "r"(a[2]), "r"(a[3]), "r"(b[0]), "r"(b[1]));
}
#define LDSM_X4(r, a) \
    asm volatile("ldmatrix.sync.aligned.m8n8.x4.shared.b16 {%0,%1,%2,%3}, [%4];" \
        : "=r"((r)[0]), "=r"((r)[1]), "=r"((r)[2]), "=r"((r)[3]) : "r"(a))

__device__ __forceinline__ uint32_t saddr(const void* p) {
    return (uint32_t)__cvta_generic_to_shared(p);
}
__device__ __forceinline__ void cp16(uint32_t s, const void* g) {
    asm volatile("cp.async.cg.shared.global [%0], [%1], 16;\n" :: "r"(s), "l"(g));
}
#define CP_COMMIT() asm volatile("cp.async.commit_group;\n")
#define CP_WAIT2()  asm volatile("cp.async.wait_group 2;\n")
#define CP_WAIT1()  asm volatile("cp.async.wait_group 1;\n")
#define CP_WAIT0()  asm volatile("cp.async.wait_group 0;\n")

__device__ __forceinline__ void bfsplit(float f, __nv_bfloat16& h, __nv_bfloat16& l) {
    h = __float2bfloat16(f);
    l = __float2bfloat16(f - __bfloat162float(h));
}

// ============================================================
// conv_x: x -> tf32 (+ block 0 computes Wg row-sums)
// ============================================================
__global__ void conv_x(const float4* __restrict__ in, uint4* __restrict__ hi, int n4,
                       const float* __restrict__ Wg, const float* __restrict__ bg)
{
    int i = blockIdx.x * blockDim.x + threadIdx.x;
    if (blockIdx.x == 0 && threadIdx.x < 64) {
        int d = threadIdx.x;
        const float* wg = Wg + d * 8;
        g_wg2[d * 2 + 0] = wg[0] + wg[1] + wg[2] + wg[3];
        g_wg2[d * 2 + 1] = wg[4] + wg[5] + wg[6] + wg[7];
        if (d == 0) {
            g_bg2[0] = bg[0] + bg[1] + bg[2] + bg[3];
            g_bg2[1] = bg[4] + bg[5] + bg[6] + bg[7];
        }
    }
    if (i >= n4) return;
    float4 v = in[i];
    uint4 h;
    h.x = f2tf(v.x); h.y = f2tf(v.y); h.z = f2tf(v.z); h.w = f2tf(v.w);
    hi[i] = h;
}

// ============================================================
// conv_w3: Wq/Wk/Wv -> tf32 (grid.z)
// ============================================================
__global__ void conv_w3(const float4* __restrict__ W0, const float4* __restrict__ W1,
                        const float4* __restrict__ W2,
                        uint4* __restrict__ o0, uint4* __restrict__ o1,
                        uint4* __restrict__ o2, int n4)
{
    int i = blockIdx.x * blockDim.x + threadIdx.x;
    if (i >= n4) return;
    const float4* in = (blockIdx.z == 0) ? W0 : (blockIdx.z == 1) ? W1 : W2;
    uint4* out = (blockIdx.z == 0) ? o0 : (blockIdx.z == 1) ? o1 : o2;
    float4 v = in[i];
    uint4 h;
    h.x = f2tf(v.x); h.y = f2tf(v.y); h.z = f2tf(v.z); h.w = f2tf(v.w);
    out[i] = h;
}

// ============================================================
// conv_woT: Wo -> Wo^T bf16 hi/lo  ([n][k], k contiguous)
// ============================================================
__global__ void conv_woT(const float* __restrict__ W,
                         __nv_bfloat16* __restrict__ th, __nv_bfloat16* __restrict__ tl)
{
    __shared__ float tile[32][33];
    int n0 = blockIdx.x * 32, k0 = blockIdx.y * 32;
    int tx = threadIdx.x, ty = threadIdx.y;
    tile[ty][tx] = W[(size_t)(k0 + ty) * D_ + n0 + tx];
    __syncthreads();
    float f = tile[tx][ty];
    __nv_bfloat16 h, l;
    bfsplit(f, h, l);
    size_t o = (size_t)(n0 + ty) * D_ + k0 + tx;
    th[o] = h; tl[o] = l;
}

// ============================================================
// Gates
// ============================================================
__global__ __launch_bounds__(256)
void gates_kernel(const float* __restrict__ x, const float* __restrict__ grep_a,
                  float* __restrict__ ga1)
{
    int w    = blockIdx.x * 8 + (threadIdx.x >> 5);
    int lane = threadIdx.x & 31;
    int bh = w >> 10, t = w & 1023;
    int b = bh / H_, h = bh % H_;
    const float* xp = x + ((size_t)b * T_ + t) * D_ + h * HD_;

    float s0 = 0.f, s1 = 0.f;
#pragma unroll
    for (int d = lane; d < HD_; d += 32) {
        float xv = xp[d];
        s0 += xv * g_wg2[d * 2 + 0];
        s1 += xv * g_wg2[d * 2 + 1];
    }
#pragma unroll
    for (int off = 16; off > 0; off >>= 1) {
        s0 += __shfl_xor_sync(0xffffffffu, s0, off);
        s1 += __shfl_xor_sync(0xffffffffu, s1, off);
    }
    if (lane == 0) {
        s0 += g_bg2[0];
        s1 += g_bg2[1];
        float ga = 1.f / (1.f + expf(-s0));
        float gb = 1.f / (1.f + expf(-s1));
        ga1[w] = ga * (gb * grep_a[h] - 1.f) + 2.f;
    }
}

// ============================================================
// Merged QKV GEMM (tf32, 1-term): out_z = tf32(x@W_z + b_z),
// head layout with per-head permutation: q,k perm4 ; v perm8.
// BM=128 BN=128 BK=16, 3-stage cp.async ring. (proven R6 core)
// ============================================================
#define QKV_STAGE 4736
__global__ __launch_bounds__(256, 2)
void gemm_qkv(const uint32_t* __restrict__ A,
              const uint32_t* __restrict__ W0, const uint32_t* __restrict__ W1,
              const uint32_t* __restrict__ W2,
              const float* __restrict__ bb0, const float* __restrict__ bb1,
              const float* __restrict__ bb2,
              uint32_t* __restrict__ o0, uint32_t* __restrict__ o1,
              uint32_t* __restrict__ o2)
{
    extern __shared__ uint32_t sm[];
    const int z = blockIdx.z;
    const uint32_t* W = (z == 0) ? W0 : (z == 1) ? W1 : W2;
    const float* bias = (z == 0) ? bb0 : (z == 1) ? bb1 : bb2;
    uint32_t* out     = (z == 0) ? o0 : (z == 1) ? o1 : o2;

    const int tid = threadIdx.x;
    const int w = tid >> 5, lane = tid & 31, g = lane >> 2, q4 = lane & 3;
    const int wm = (w & 1) * 64, wn = (w >> 1) * 32;
    const int row0 = blockIdx.x * 128, col0 = blockIdx.y * 128;

    float acc[4][4][4];
#pragma unroll
    for (int i = 0; i < 4; i++)
#pragma unroll
        for (int f = 0; f < 4; f++)
#pragma unroll
            for (int e = 0; e < 4; e++) acc[i][f][e] = 0.f;

#define QKV_STAGE_LOAD(s, k0) do {                                             \
    uint32_t* As_ = sm + (s) * QKV_STAGE;                                      \
    uint32_t* Bs_ = As_ + 2560;                                                \
    _Pragma("unroll")                                                          \
    for (int i = 0; i < 2; i++) {                                              \
        int idx = tid + i * 256;                                               \
        int m = idx >> 2, kc = (idx & 3) * 4;                                  \
        cp16(saddr(&As_[m * 20 + kc]), A + (size_t)(row0 + m) * D_ + (k0) + kc); \
        int kk = idx >> 5, n4 = (idx & 31) * 4;                                \
        cp16(saddr(&Bs_[kk * 136 + n4]), W + (size_t)((k0) + kk) * D_ + col0 + n4); \
    } } while (0)

    QKV_STAGE_LOAD(0, 0);  CP_COMMIT();
    QKV_STAGE_LOAD(1, 16); CP_COMMIT();
    QKV_STAGE_LOAD(2, 32); CP_COMMIT();

    int st = 0;
    for (int kb = 0; kb < 48; kb++) {
        if (kb + 2 < 48) CP_WAIT2(); else CP_WAIT0();
        __syncthreads();
        const uint32_t* As = sm + st * QKV_STAGE;
        const uint32_t* Bs = As + 2560;
#pragma unroll
        for (int s = 0; s < 2; s++) {
            int kc = 8 * s + q4;
            uint32_t af[4][4], bf2[4][2];
#pragma unroll
            for (int i = 0; i < 4; i++) {
                int r = wm + 16 * i + g;
                af[i][0] = As[r * 20 + kc];       af[i][1] = As[(r + 8) * 20 + kc];
                af[i][2] = As[r * 20 + kc + 4];   af[i][3] = As[(r + 8) * 20 + kc + 4];
            }
#pragma unroll
            for (int f = 0; f < 4; f++) {
                int n = wn + 8 * f + g;
                bf2[f][0] = Bs[kc * 136 + n];
                bf2[f][1] = Bs[(kc + 4) * 136 + n];
            }
#pragma unroll
            for (int i = 0; i < 4; i++)
#pragma unroll
                for (int f = 0; f < 4; f++) mma_tf32(acc[i][f], af[i], bf2[f]);
        }
        __syncthreads();
        if (kb + 3 < 48) { QKV_STAGE_LOAD(st, (kb + 3) * 16); CP_COMMIT(); }
        st++; if (st == 3) st = 0;
    }

    // epilogue: +bias, tf32, head layout with perm4 (q,k) / perm8 (v)
#pragma unroll
    for (int i = 0; i < 4; i++)
#pragma unroll
        for (int f = 0; f < 4; f++) {
            int col = col0 + wn + 8 * f + 2 * q4;
            float b0 = bias[col], b1 = bias[col + 1];
            int hh = col >> 6;
            int hd0 = col & 63, hd1 = hd0 + 1;
            int hp0, hp1;
            if (z == 2) { hp0 = 8 * (hd0 & 7) + (hd0 >> 3); hp1 = 8 * (hd1 & 7) + (hd1 >> 3); }
            else        { hp0 = 16 * (hd0 & 3) + (hd0 >> 2); hp1 = 16 * (hd1 & 3) + (hd1 >> 2); }
#pragma unroll
            for (int half = 0; half < 2; half++) {
                int row = row0 + wm + 16 * i + g + 8 * half;
                int bb = row >> 10, tt = row & 1023;
                uint32_t* dst = out + ((size_t)(bb * H_ + hh) * T_ + tt) * HD_;
                dst[hp0] = f2tf(acc[i][f][2 * half + 0] + b0);
                dst[hp1] = f2tf(acc[i][f][2 * half + 1] + b1);
            }
        }
}

// ============================================================
// Flash attention: paired-tile softmax, split cp waits, vectorized frags.
// smem (words): per stage 8960 = Ks[32][80] (blocks of 20) + Vs[32][68] + RB[32][132]
//   x2 stages = 17920 ; Pp[128][36] = 4608 ; Ms 1024  => 23552 w = 94208 B
// ============================================================
#define STG_W 8960
#define C_SM (0.125f * 1.44269504088896340736f)   /* 0.125*log2(e) */
__global__ __launch_bounds__(256, 2)
void attn_kernel(const float* __restrict__ rel_bias,
                 const float* __restrict__ attn_mask)
{
    extern __shared__ float smf[];
    uint32_t* Pp = (uint32_t*)(smf + 2 * STG_W);   // [128][36], permuted cols
    float*    Ms = smf + 2 * STG_W + 4608;         // [1024]

    const int tid  = threadIdx.x;
    const int w    = tid >> 5;
    const int lane = tid & 31;
    const int g    = lane >> 2;
    const int q4   = lane & 3;
    const int qb   = 16 * w;
    const int q0   = blockIdx.x * 128;
    const int bh   = blockIdx.y;
    const int b    = bh / H_, h = bh % H_;

    const uint32_t* qptr = g_q + (size_t)bh * T_ * HD_;
    const uint32_t* kptr = g_k + (size_t)bh * T_ * HD_;
    const uint32_t* vptr = g_v + (size_t)bh * T_ * HD_;

    const int r0 = qb + g;
    const int r1 = qb + g + 8;

#define ATT_STAGE_LOAD(s, k0) do {                                             \
    uint32_t* Ks_ = (uint32_t*)(smf + (s) * STG_W);                            \
    uint32_t* Vs_ = Ks_ + 2560;                                                \
    float*    RB_ = smf + (s) * STG_W + 4736;                                  \
    _Pragma("unroll")                                                          \
    for (int i = 0; i < 2; i++) {                                              \
        int idx = tid + i * 256;                                               \
        int kk = idx >> 4, m = idx & 15;                                       \
        cp16(saddr(&Ks_[kk * 80 + 20 * (m >> 2) + 4 * (m & 3)]),               \
             kptr + (size_t)((k0) + kk) * HD_ + 4 * m);                        \
        cp16(saddr(&Vs_[kk * 68 + 4 * m]),                                     \
             vptr + (size_t)((k0) + kk) * HD_ + 4 * m);                        \
    }                                                                          \
    const float* rbp_ = rel_bias + ((size_t)bh * T_ + (k0)) * T_ + q0;         \
    _Pragma("unroll")                                                          \
    for (int i = 0; i < 4; i++) {                                              \
        int idx = tid + i * 256;                                               \
        int kk = idx >> 5, qq = (idx & 31) * 4;                                \
        cp16(saddr(&RB_[kk * 132 + qq]), rbp_ + (size_t)kk * T_ + qq);         \
    } } while (0)

#define ATT_QK(stg, k0, sacc) do {                                             \
    const uint32_t* Ks = (const uint32_t*)(smf + (stg) * STG_W);               \
    const float*    RB = smf + (stg) * STG_W + 4736;                           \
    _Pragma("unroll")                                                          \
    for (int f = 0; f < 4; f++) {                                              \
        int c0 = 8 * f + 2 * q4;                                               \
        sacc[f][0] = 8.f * fmaf(ga0,  RB[c0 * 132 + r0],       Ms[(k0) + c0]); \
        sacc[f][1] = 8.f * fmaf(ga0,  RB[(c0 + 1) * 132 + r0], Ms[(k0) + c0 + 1]); \
        sacc[f][2] = 8.f * fmaf(ga1v, RB[c0 * 132 + r1],       Ms[(k0) + c0]); \
        sacc[f][3] = 8.f * fmaf(ga1v, RB[(c0 + 1) * 132 + r1], Ms[(k0) + c0 + 1]); \
    }                                                                          \
    _Pragma("unroll")                                                          \
    for (int j = 0; j < 4; j++) {                                              \
        uint4 kf[4];                                                           \
        _Pragma("unroll")                                                      \
        for (int f = 0; f < 4; f++)                                            \
            kf[f] = *(const uint4*)&Ks[(8 * f + g) * 80 + 20 * q4 + 4 * j];    \
        _Pragma("unroll")                                                      \
        for (int f = 0; f < 4; f++) {                                          \
            uint32_t b0[2] = { kf[f].x, kf[f].y };                             \
            mma_tf32(sacc[f], qf[2 * j], b0);                                  \
            uint32_t b1[2] = { kf[f].z, kf[f].w };                             \
            mma_tf32(sacc[f], qf[2 * j + 1], b1);                              \
        }                                                                      \
    }                                                                          \
    _Pragma("unroll")                                                          \
    for (int f = 0; f < 4; f++)                                                \
        _Pragma("unroll")                                                      \
        for (int e = 0; e < 4; e++) sacc[f][e] *= C_SM;                        \
    } while (0)

#define ATT_PV(stg, sacc) do {                                                 \
    const uint32_t* Vs = (const uint32_t*)(smf + (stg) * STG_W) + 2560;        \
    _Pragma("unroll")                                                          \
    for (int f = 0; f < 4; f++) {                                              \
        int pb  = 8 * ((2 * q4) & 3)     + 2 * f + (q4 >> 1);                  \
        int pb2 = 8 * ((2 * q4 + 1) & 3) + 2 * f + (q4 >> 1);                  \
        Pp[r0 * 36 + pb]  = f2tf(sacc[f][0]);                                  \
        Pp[r0 * 36 + pb2] = f2tf(sacc[f][1]);                                  \
        Pp[r1 * 36 + pb]  = f2tf(sacc[f][2]);                                  \
        Pp[r1 * 36 + pb2] = f2tf(sacc[f][3]);                                  \
    }                                                                          \
    __syncwarp();                                                              \
    uint4 p0a = *(const uint4*)&Pp[r0 * 36 + 8 * q4];                          \
    uint4 p0b = *(const uint4*)&Pp[r0 * 36 + 8 * q4 + 4];                      \
    uint4 p1a = *(const uint4*)&Pp[r1 * 36 + 8 * q4];                          \
    uint4 p1b = *(const uint4*)&Pp[r1 * 36 + 8 * q4 + 4];                      \
    uint32_t pw0[8] = { p0a.x, p0a.y, p0a.z, p0a.w, p0b.x, p0b.y, p0b.z, p0b.w }; \
    uint32_t pw1[8] = { p1a.x, p1a.y, p1a.z, p1a.w, p1b.x, p1b.y, p1b.z, p1b.w }; \
    _Pragma("unroll")                                                          \
    for (int s = 0; s < 4; s++) {                                              \
        uint32_t pa[4] = { pw0[2 * s], pw1[2 * s], pw0[2 * s + 1], pw1[2 * s + 1] }; \
        int rowA = (8 * s + q4) * 68, rowB = (8 * s + q4 + 4) * 68;            \
        uint4 v0a = *(const uint4*)&Vs[rowA + 8 * g];                          \
        uint4 v0b = *(const uint4*)&Vs[rowA + 8 * g + 4];                      \
        uint4 v1a = *(const uint4*)&Vs[rowB + 8 * g];                          \
        uint4 v1b = *(const uint4*)&Vs[rowB + 8 * g + 4];                      \
        uint32_t va[8] = { v0a.x, v0a.y, v0a.z, v0a.w, v0b.x, v0b.y, v0b.z, v0b.w }; \
        uint32_t vc[8] = { v1a.x, v1a.y, v1a.z, v1a.w, v1b.x, v1b.y, v1b.z, v1b.w }; \
        _Pragma("unroll")                                                      \
        for (int f = 0; f < 8; f++) {                                          \
            uint32_t vb[2] = { va[f], vc[f] };                                 \
            mma_tf32(oacc[f], pa, vb);                                         \
        }                                                                      \
    } } while (0)

    // prologue: stage 0 (+mask), stage 1
    ATT_STAGE_LOAD(0, 0);
    cp16(saddr(&Ms[tid * 4]), attn_mask + (size_t)b * T_ + tid * 4);
    CP_COMMIT();
    ATT_STAGE_LOAD(1, 32);
    CP_COMMIT();

    // Q fragments from perm4 gmem: 8 x LDG.128
    uint32_t qf[8][4];
    {
        const uint32_t* qa = qptr + (size_t)(q0 + r0) * HD_ + 16 * q4;
        const uint32_t* qc = qptr + (size_t)(q0 + r1) * HD_ + 16 * q4;
#pragma unroll
        for (int t = 0; t < 4; t++) {
            uint4 va = *(const uint4*)(qa + 4 * t);
            uint4 vc = *(const uint4*)(qc + 4 * t);
            qf[2 * t][0] = va.x; qf[2 * t][2] = va.y;
            qf[2 * t + 1][0] = va.z; qf[2 * t + 1][2] = va.w;
            qf[2 * t][1] = vc.x; qf[2 * t][3] = vc.y;
            qf[2 * t + 1][1] = vc.z; qf[2 * t + 1][3] = vc.w;
        }
    }
    const float ga0  = g_ga1[(size_t)bh * T_ + q0 + r0];
    const float ga1v = g_ga1[(size_t)bh * T_ + q0 + r1];

    float m_[2] = {-INFINITY, -INFINITY};
    float l_[2] = {0.f, 0.f};
    float oacc[8][4];
#pragma unroll
    for (int f = 0; f < 8; f++)
#pragma unroll
        for (int e = 0; e < 4; e++) oacc[f][e] = 0.f;

    for (int p = 0; p < 16; p++) {
        const int k0 = p * 64;
        CP_WAIT1();
        __syncthreads();                 // stage 0 resident
        float sacc0[4][4], sacc1[4][4];
        ATT_QK(0, k0, sacc0);
        CP_WAIT0();
        __syncthreads();                 // stage 1 resident
        ATT_QK(1, k0 + 32, sacc1);

        // ---- combined softmax over 64 cols ----
        float mt0 = sacc0[0][0], mt1 = sacc0[0][2];
#pragma unroll
        for (int f = 0; f < 4; f++) {
            mt0 = fmaxf(mt0, fmaxf(fmaxf(sacc0[f][0], sacc0[f][1]),
                                   fmaxf(sacc1[f][0], sacc1[f][1])));
            mt1 = fmaxf(mt1, fmaxf(fmaxf(sacc0[f][2], sacc0[f][3]),
                                   fmaxf(sacc1[f][2], sacc1[f][3])));
        }
        mt0 = fmaxf(mt0, __shfl_xor_sync(0xffffffffu, mt0, 1));
        mt0 = fmaxf(mt0, __shfl_xor_sync(0xffffffffu, mt0, 2));
        mt1 = fmaxf(mt1, __shfl_xor_sync(0xffffffffu, mt1, 1));
        mt1 = fmaxf(mt1, __shfl_xor_sync(0xffffffffu, mt1, 2));

        float mn0 = fmaxf(m_[0], mt0), mn1 = fmaxf(m_[1], mt1);
        float al0 = exp2f(m_[0] - mn0), al1 = exp2f(m_[1] - mn1);
        m_[0] = mn0; m_[1] = mn1;

        float ls0 = 0.f, ls1 = 0.f;
#pragma unroll
        for (int f = 0; f < 4; f++) {
            sacc0[f][0] = exp2f(sacc0[f][0] - mn0);
            sacc0[f][1] = exp2f(sacc0[f][1] - mn0);
            sacc0[f][2] = exp2f(sacc0[f][2] - mn1);
            sacc0[f][3] = exp2f(sacc0[f][3] - mn1);
            sacc1[f][0] = exp2f(sacc1[f][0] - mn0);
            sacc1[f][1] = exp2f(sacc1[f][1] - mn0);
            sacc1[f][2] = exp2f(sacc1[f][2] - mn1);
            sacc1[f][3] = exp2f(sacc1[f][3] - mn1);
            ls0 += sacc0[f][0] + sacc0[f][1] + sacc1[f][0] + sacc1[f][1];
            ls1 += sacc0[f][2] + sacc0[f][3] + sacc1[f][2] + sacc1[f][3];
        }
        ls0 += __shfl_xor_sync(0xffffffffu, ls0, 1);
        ls0 += __shfl_xor_sync(0xffffffffu, ls0, 2);
        ls1 += __shfl_xor_sync(0xffffffffu, ls1, 1);
        ls1 += __shfl_xor_sync(0xffffffffu, ls1, 2);
        l_[0] = l_[0] * al0 + ls0;
        l_[1] = l_[1] * al1 + ls1;
#pragma unroll
        for (int f = 0; f < 8; f++) {
            oacc[f][0] *= al0; oacc[f][1] *= al0;
            oacc[f][2] *= al1; oacc[f][3] *= al1;
        }

        // ---- PV tile 0, refill stage 0, PV tile 1, refill stage 1 ----
        ATT_PV(0, sacc0);
        __syncthreads();
        if (p < 15) { ATT_STAGE_LOAD(0, k0 + 64); CP_COMMIT(); }
        ATT_PV(1, sacc1);
        __syncthreads();
        if (p < 15) { ATT_STAGE_LOAD(1, k0 + 96); CP_COMMIT(); }
    }

    // ---- finalize: O /= l ; write bf16 hi/lo row-major [b*t][h*64+hd] ----
    float inv0 = 1.f / l_[0], inv1 = 1.f / l_[1];
#pragma unroll
    for (int f = 0; f < 8; f++) {
        int c = 8 * f + 2 * q4;
        size_t i0 = ((size_t)b * T_ + q0 + r0) * D_ + h * HD_ + c;
        size_t i1 = ((size_t)b * T_ + q0 + r1) * D_ + h * HD_ + c;
        float v00 = oacc[f][0] * inv0, v01 = oacc[f][1] * inv0;
        float v10 = oacc[f][2] * inv1, v11 = oacc[f][3] * inv1;
        __nv_bfloat16 h00,l00,h01,l01,h10,l10,h11,l11;
        bfsplit(v00,h00,l00); bfsplit(v01,h01,l01);
        bfsplit(v10,h10,l10); bfsplit(v11,h11,l11);
        *(__nv_bfloat162*)(g_oh + i0) = {h00, h01};
        *(__nv_bfloat162*)(g_ol + i0) = {l00, l01};
        *(__nv_bfloat162*)(g_oh + i1) = {h10, h11};
        *(__nv_bfloat162*)(g_ol + i1) = {l10, l11};
    }
}

// ============================================================
// O-proj GEMM, bf16 3-term with ldmatrix (proven R6/R7 kernel).
// ============================================================
#define OB_STAGE 40960
__global__ __launch_bounds__(256, 2)
void gemm_o3(const __nv_bfloat16* __restrict__ Ah, const __nv_bfloat16* __restrict__ Al,
             const __nv_bfloat16* __restrict__ Bh, const __nv_bfloat16* __restrict__ Bl,
             const float* __restrict__ bias, float* __restrict__ out)
{
    extern __shared__ char smo[];
    const int tid = threadIdx.x;
    const int w = tid >> 5, lane = tid & 31, g = lane >> 2, q4 = lane & 3;
    const int wm = (w & 1) * 64, wn = (w >> 1) * 32;
    const int row0 = blockIdx.x * 128, col0 = blockIdx.y * 128;

    float acc[4][4][4];
#pragma unroll
    for (int i = 0; i < 4; i++)
#pragma unroll
        for (int f = 0; f < 4; f++)
#pragma unroll
            for (int e = 0; e < 4; e++) acc[i][f][e] = 0.f;

    const int lrow = lane & 15;
    const int lchk = (lane >> 4) * 16;

#define O3_STAGE_LOAD(s, k0) do {                                              \
    char* base_ = smo + (s) * OB_STAGE;                                        \
    _Pragma("unroll")                                                          \
    for (int i = 0; i < 2; i++) {                                              \
        int idx = tid + i * 256;                                               \
        int r = idx >> 2, ch = idx & 3;                                        \
        uint32_t so = saddr(base_ + r * 80 + ch * 16);                         \
        cp16(so,         Ah + (size_t)(row0 + r) * D_ + (k0) + ch * 8);        \
        cp16(so + 10240, Al + (size_t)(row0 + r) * D_ + (k0) + ch * 8);        \
        cp16(so + 20480, Bh + (size_t)(col0 + r) * D_ + (k0) + ch * 8);        \
        cp16(so + 30720, Bl + (size_t)(col0 + r) * D_ + (k0) + ch * 8);        \
    } } while (0)

    O3_STAGE_LOAD(0, 0);  CP_COMMIT();
    O3_STAGE_LOAD(1, 32); CP_COMMIT();

    for (int kb = 0; kb < 24; kb++) {
        if (kb + 1 < 24) CP_WAIT1(); else CP_WAIT0();
        __syncthreads();
        char* base = smo + (kb & 1) * OB_STAGE;
#pragma unroll
        for (int ks = 0; ks < 2; ks++) {
            uint32_t ah[4][4], al[4][4];
#pragma unroll
            for (int i = 0; i < 4; i++) {
                uint32_t a = saddr(base + (wm + 16 * i + lrow) * 80 + ks * 32 + lchk);
                LDSM_X4(ah[i], a);
                LDSM_X4(al[i], a + 10240);
            }
            uint32_t bh4[2][4], bl4[2][4];
#pragma unroll
            for (int j = 0; j < 2; j++) {
                uint32_t a = saddr(base + 20480 + (wn + 16 * j + lrow) * 80 + ks * 32 + lchk);
                LDSM_X4(bh4[j], a);
                LDSM_X4(bl4[j], a + 10240);
            }
#pragma unroll
            for (int i = 0; i < 4; i++)
#pragma unroll
                for (int f = 0; f < 4; f++) {
                    uint32_t bhf[2] = { bh4[f >> 1][f & 1], bh4[f >> 1][(f & 1) + 2] };
                    uint32_t blf[2] = { bl4[f >> 1][f & 1], bl4[f >> 1][(f & 1) + 2] };
                    mma_bf16(acc[i][f], ah[i], bhf);
                    mma_bf16(acc[i][f], ah[i], blf);
                    mma_bf16(acc[i][f], al[i], bhf);
                }
        }
        __syncthreads();
        if (kb + 2 < 24) { O3_STAGE_LOAD(kb & 1, (kb + 2) * 32); CP_COMMIT(); }
    }

#pragma unroll
    for (int i = 0; i < 4; i++)
#pragma unroll
        for (int f = 0; f < 4; f++) {
            int col = col0 + wn + 8 * f + 2 * q4;
            float b0 = bias[col], b1 = bias[col + 1];
#pragma unroll
            for (int half = 0; half < 2; half++) {
                int row = row0 + wm + 16 * i + g + 8 * half;
                float2 v;
                v.x = acc[i][f][2 * half + 0] + b0;
                v.y = acc[i][f][2 * half + 1] + b1;
                *(float2*)(out + (size_t)row * D_ + col) = v;
            }
        }
}

// ============================================================
extern "C" void kernel_launch(void* const* d_in, const int* in_sizes, int n_in,
                              void* d_out, int out_size)
{
    const float* x         = (const float*)d_in[0];
    const float* attn_mask = (const float*)d_in[1];
    const float* rel_bias  = (const float*)d_in[2];
    const float* Wq = (const float*)d_in[3];
    const float* bq = (const float*)d_in[4];
    const float* Wk = (const float*)d_in[5];
    const float* bk = (const float*)d_in[6];
    const float* Wv = (const float*)d_in[7];
    const float* bv = (const float*)d_in[8];
    const float* Wo = (const float*)d_in[9];
    const float* bo = (const float*)d_in[10];
    const float* Wg = (const float*)d_in[11];
    const float* bg = (const float*)d_in[12];
    const float* grep_a = (const float*)d_in[13];
    float* out = (float*)d_out;

    uint32_t *xhi, *wqh, *wkh, *wvh, *q, *k, *v;
    __nv_bfloat16 *woth, *wotl, *oh, *ol;
    float *ga1;
    cudaGetSymbolAddress((void**)&xhi,  g_xhi);
    cudaGetSymbolAddress((void**)&wqh,  g_wqh);
    cudaGetSymbolAddress((void**)&wkh,  g_wkh);
    cudaGetSymbolAddress((void**)&wvh,  g_wvh);
    cudaGetSymbolAddress((void**)&woth, g_woth);
    cudaGetSymbolAddress((void**)&wotl, g_wotl);
    cudaGetSymbolAddress((void**)&q,    g_q);
    cudaGetSymbolAddress((void**)&k,    g_k);
    cudaGetSymbolAddress((void**)&v,    g_v);
    cudaGetSymbolAddress((void**)&oh,   g_oh);
    cudaGetSymbolAddress((void**)&ol,   g_ol);
    cudaGetSymbolAddress((void**)&ga1,  g_ga1);

    cudaFuncSetAttribute(gemm_qkv,    cudaFuncAttributeMaxDynamicSharedMemorySize, QKV_STAGE * 3 * 4);
    cudaFuncSetAttribute(attn_kernel, cudaFuncAttributeMaxDynamicSharedMemorySize, 94208);
    cudaFuncSetAttribute(gemm_o3,     cudaFuncAttributeMaxDynamicSharedMemorySize, OB_STAGE * 2);

    const int nx4 = N_ * D_ / 4;
    const int nw4 = D_ * D_ / 4;
    conv_x<<<(nx4 + 255) / 256, 256>>>((const float4*)x, (uint4*)xhi, nx4, Wg, bg);    // 0
    conv_w3<<<dim3((nw4 + 255) / 256, 1, 3), 256>>>(                                    // 1
        (const float4*)Wq, (const float4*)Wk, (const float4*)Wv,
        (uint4*)wqh, (uint4*)wkh, (uint4*)wvh, nw4);
    conv_woT<<<dim3(24, 24), dim3(32, 32)>>>(Wo, woth, wotl);                           // 2
    gates_kernel<<<BH_ * T_ / 8, 256>>>(x, grep_a, ga1);                                // 3
    gemm_qkv<<<dim3(64, 6, 3), 256, QKV_STAGE * 3 * 4>>>(                               // 4
        xhi, wqh, wkh, wvh, bq, bk, bv, q, k, v);
    attn_kernel<<<dim3(T_ / 128, BH_), 256, 94208>>>(rel_bias, attn_mask);              // 5
    gemm_o3<<<dim3(64, 6), 256, OB_STAGE * 2>>>(oh, ol, woth, wotl, bo, out);           // 6
}

// round 9
// speedup vs baseline: 1.1758x; 1.0755x over previous
#include <cuda_runtime.h>
#include <cuda_bf16.h>
#include <math.h>
#include <stdint.h>

#define B_  8
#define T_  1024
#define D_  768
#define H_  12
#define HD_ 64
#define BH_ (B_*H_)   /* 96 */
#define N_  (B_*T_)   /* 8192 */
#define WSZ_ ((size_t)D_*D_)
#define C_SM  (0.125f * 1.44269504088896340736f)   /* 0.125*log2(e) */
#define K8C   (1.44269504088896340736f)            /* 8*C_SM = log2(e) */

// ---- scratch (static device globals; no allocation) ----
__device__ uint32_t g_xhi[N_*D_];          // x tf32
__device__ uint32_t g_wqh[D_*D_];          // Wq tf32
__device__ uint32_t g_wkh[D_*D_];
__device__ uint32_t g_wvh[D_*D_];
__device__ __nv_bfloat16 g_woth[D_*D_];    // Wo^T bf16 hi [n][k]
__device__ __nv_bfloat16 g_wotl[D_*D_];    // Wo^T bf16 lo
__device__ uint32_t g_q[BH_*T_*HD_];       // tf32 (pre-scaled by C_SM), head layout
__device__ uint32_t g_k[BH_*T_*HD_];       // tf32, head layout
__device__ uint32_t g_v[BH_*T_*HD_];       // tf32, head layout
__device__ __nv_bfloat16 g_oh[N_*D_];      // attn out hi bf16, row-major
__device__ __nv_bfloat16 g_ol[N_*D_];      // attn out lo
__device__ float    g_ga1[BH_*T_];         // log2e * ga1
__device__ float    g_msk[N_];             // log2e * attn_mask  [b][t]
__device__ float    g_wg2[HD_*2];
__device__ float    g_bg2[2];

// ---- helpers ----
__device__ __forceinline__ uint32_t f2tf(float f) {
    uint32_t u;
    asm("cvt.rna.tf32.f32 %0, %1;" : "=r"(u) : "f"(f));
    return u;
}
__device__ __forceinline__ void mma_tf32(float* d, const uint32_t* a, const uint32_t* b) {
    asm volatile(
        "mma.sync.aligned.m16n8k8.row.col.f32.tf32.tf32.f32 "
        "{%0,%1,%2,%3}, {%4,%5,%6,%7}, {%8,%9}, {%0,%1,%2,%3};\n"
        : "+f"(d[0]), "+f"(d[1]), "+f"(d[2]), "+f"(d[3])
        : "r"(a[0]), "r"(a[1]), "r"(a[2]), "r"(a[3]), "r"(b[0]), "r"(b[1]));
}
__device__ __forceinline__ void mma_bf16(float* d, const uint32_t* a, const uint32_t* b) {
    asm volatile(
        "mma.sync.aligned.m16n8k16.row.col.f32.bf16.bf16.f32 "
        "{%0,%1,%2,%3}, {%4,%5,%6,%7}, {%8,%9}, {%0,%1,%2,%3};\n"
        : "+f"(d[0]), "+f"(d[1]), "+f"(d[2]), "+f"(d[3])
        : "r"(a[0]), "r"(a[1]), "r"(a[2]), "r"(a[3]), "r"(b[0]), "r"(b[1]));
}
#define LDSM_X4(r, a) \
    asm volatile("ldmatrix.sync.aligned.m8n8.x4.shared.b16 {%0,%1,%2,%3}, [%4];" \
        : "=r"((r)[0]), "=r"((r)[1]), "=r"((r)[2]), "=r"((r)[3]) : "r"(a))

__device__ __forceinline__ uint32_t saddr(const void* p) {
    return (uint32_t)__cvta_generic_to_shared(p);
}
__device__ __forceinline__ void cp16(uint32_t s, const void* g) {
    asm volatile("cp.async.cg.shared.global [%0], [%1], 16;\n" :: "r"(s), "l"(g));
}
#define CP_COMMIT() asm volatile("cp.async.commit_group;\n")
#define CP_WAIT2()  asm volatile("cp.async.wait_group 2;\n")
#define CP_WAIT1()  asm volatile("cp.async.wait_group 1;\n")
#define CP_WAIT0()  asm volatile("cp.async.wait_group 0;\n")

__device__ __forceinline__ void bfsplit(float f, __nv_bfloat16& h, __nv_bfloat16& l) {
    h = __float2bfloat16(f);
    l = __float2bfloat16(f - __bfloat162float(h));
}

// ============================================================
// conv_x: x -> tf32 (+ block 0 computes Wg row-sums)
// ============================================================
__global__ void conv_x(const float4* __restrict__ in, uint4* __restrict__ hi, int n4,
                       const float* __restrict__ Wg, const float* __restrict__ bg)
{
    int i = blockIdx.x * blockDim.x + threadIdx.x;
    if (blockIdx.x == 0 && threadIdx.x < 64) {
        int d = threadIdx.x;
        const float* wg = Wg + d * 8;
        g_wg2[d * 2 + 0] = wg[0] + wg[1] + wg[2] + wg[3];
        g_wg2[d * 2 + 1] = wg[4] + wg[5] + wg[6] + wg[7];
        if (d == 0) {
            g_bg2[0] = bg[0] + bg[1] + bg[2] + bg[3];
            g_bg2[1] = bg[4] + bg[5] + bg[6] + bg[7];
        }
    }
    if (i >= n4) return;
    float4 v = in[i];
    uint4 h;
    h.x = f2tf(v.x); h.y = f2tf(v.y); h.z = f2tf(v.z); h.w = f2tf(v.w);
    hi[i] = h;
}

// ============================================================
// conv_w3: Wq/Wk/Wv -> tf32 (grid.z)
// ============================================================
__global__ void conv_w3(const float4* __restrict__ W0, const float4* __restrict__ W1,
                        const float4* __restrict__ W2,
                        uint4* __restrict__ o0, uint4* __restrict__ o1,
                        uint4* __restrict__ o2, int n4)
{
    int i = blockIdx.x * blockDim.x + threadIdx.x;
    if (i >= n4) return;
    const float4* in = (blockIdx.z == 0) ? W0 : (blockIdx.z == 1) ? W1 : W2;
    uint4* out = (blockIdx.z == 0) ? o0 : (blockIdx.z == 1) ? o1 : o2;
    float4 v = in[i];
    uint4 h;
    h.x = f2tf(v.x); h.y = f2tf(v.y); h.z = f2tf(v.z); h.w = f2tf(v.w);
    out[i] = h;
}

// ============================================================
// conv_woT: Wo -> Wo^T bf16 hi/lo ([n][k], k contiguous)
// ============================================================
__global__ void conv_woT(const float* __restrict__ W,
                         __nv_bfloat16* __restrict__ th, __nv_bfloat16* __restrict__ tl)
{
    __shared__ float tile[32][33];
    int n0 = blockIdx.x * 32, k0 = blockIdx.y * 32;
    int tx = threadIdx.x, ty = threadIdx.y;
    tile[ty][tx] = W[(size_t)(k0 + ty) * D_ + n0 + tx];
    __syncthreads();
    float f = tile[tx][ty];
    __nv_bfloat16 h, l;
    bfsplit(f, h, l);
    size_t o = (size_t)(n0 + ty) * D_ + k0 + tx;
    th[o] = h; tl[o] = l;
}

// ============================================================
// Gates: emits log2e*ga1 ; first blocks also pre-scale the mask.
// ============================================================
__global__ __launch_bounds__(256)
void gates_kernel(const float* __restrict__ x, const float* __restrict__ grep_a,
                  const float* __restrict__ attn_mask, float* __restrict__ ga1)
{
    int gidx = blockIdx.x * 256 + threadIdx.x;
    if (gidx < N_) g_msk[gidx] = K8C * attn_mask[gidx];

    int w    = blockIdx.x * 8 + (threadIdx.x >> 5);
    int lane = threadIdx.x & 31;
    int bh = w >> 10, t = w & 1023;
    int b = bh / H_, h = bh % H_;
    const float* xp = x + ((size_t)b * T_ + t) * D_ + h * HD_;

    float s0 = 0.f, s1 = 0.f;
#pragma unroll
    for (int d = lane; d < HD_; d += 32) {
        float xv = xp[d];
        s0 += xv * g_wg2[d * 2 + 0];
        s1 += xv * g_wg2[d * 2 + 1];
    }
#pragma unroll
    for (int off = 16; off > 0; off >>= 1) {
        s0 += __shfl_xor_sync(0xffffffffu, s0, off);
        s1 += __shfl_xor_sync(0xffffffffu, s1, off);
    }
    if (lane == 0) {
        s0 += g_bg2[0];
        s1 += g_bg2[1];
        float ga = 1.f / (1.f + expf(-s0));
        float gb = 1.f / (1.f + expf(-s1));
        ga1[w] = K8C * (ga * (gb * grep_a[h] - 1.f) + 2.f);
    }
}

// ============================================================
// Merged QKV GEMM (tf32, 1-term): out_z = tf32(x@W_z + b_z), head layout.
// Q (z==0) pre-scaled by C_SM. BM=128 BN=128 BK=16, 3-stage ring.
// ============================================================
#define QKV_STAGE 4736
__global__ __launch_bounds__(256, 2)
void gemm_qkv(const uint32_t* __restrict__ A,
              const uint32_t* __restrict__ W0, const uint32_t* __restrict__ W1,
              const uint32_t* __restrict__ W2,
              const float* __restrict__ bb0, const float* __restrict__ bb1,
              const float* __restrict__ bb2,
              uint32_t* __restrict__ o0, uint32_t* __restrict__ o1,
              uint32_t* __restrict__ o2)
{
    extern __shared__ uint32_t sm[];
    const int z = blockIdx.z;
    const uint32_t* W = (z == 0) ? W0 : (z == 1) ? W1 : W2;
    const float* bias = (z == 0) ? bb0 : (z == 1) ? bb1 : bb2;
    uint32_t* out     = (z == 0) ? o0 : (z == 1) ? o1 : o2;
    const float oscale = (z == 0) ? C_SM : 1.f;

    const int tid = threadIdx.x;
    const int w = tid >> 5, lane = tid & 31, g = lane >> 2, q4 = lane & 3;
    const int wm = (w & 1) * 64, wn = (w >> 1) * 32;
    const int row0 = blockIdx.x * 128, col0 = blockIdx.y * 128;

    float acc[4][4][4];
#pragma unroll
    for (int i = 0; i < 4; i++)
#pragma unroll
        for (int f = 0; f < 4; f++)
#pragma unroll
            for (int e = 0; e < 4; e++) acc[i][f][e] = 0.f;

#define QKV_STAGE_LOAD(s, k0) do {                                             \
    uint32_t* As_ = sm + (s) * QKV_STAGE;                                      \
    uint32_t* Bs_ = As_ + 2560;                                                \
    _Pragma("unroll")                                                          \
    for (int i = 0; i < 2; i++) {                                              \
        int idx = tid + i * 256;                                               \
        int m = idx >> 2, kc = (idx & 3) * 4;                                  \
        cp16(saddr(&As_[m * 20 + kc]), A + (size_t)(row0 + m) * D_ + (k0) + kc); \
        int kk = idx >> 5, n4 = (idx & 31) * 4;                                \
        cp16(saddr(&Bs_[kk * 136 + n4]), W + (size_t)((k0) + kk) * D_ + col0 + n4); \
    } } while (0)

    QKV_STAGE_LOAD(0, 0);  CP_COMMIT();
    QKV_STAGE_LOAD(1, 16); CP_COMMIT();
    QKV_STAGE_LOAD(2, 32); CP_COMMIT();

    int st = 0;
    for (int kb = 0; kb < 48; kb++) {
        if (kb + 2 < 48) CP_WAIT2(); else CP_WAIT0();
        __syncthreads();
        const uint32_t* As = sm + st * QKV_STAGE;
        const uint32_t* Bs = As + 2560;
#pragma unroll
        for (int s = 0; s < 2; s++) {
            int kc = 8 * s + q4;
            uint32_t af[4][4], bf2[4][2];
#pragma unroll
            for (int i = 0; i < 4; i++) {
                int r = wm + 16 * i + g;
                af[i][0] = As[r * 20 + kc];       af[i][1] = As[(r + 8) * 20 + kc];
                af[i][2] = As[r * 20 + kc + 4];   af[i][3] = As[(r + 8) * 20 + kc + 4];
            }
#pragma unroll
            for (int f = 0; f < 4; f++) {
                int n = wn + 8 * f + g;
                bf2[f][0] = Bs[kc * 136 + n];
                bf2[f][1] = Bs[(kc + 4) * 136 + n];
            }
#pragma unroll
            for (int i = 0; i < 4; i++)
#pragma unroll
                for (int f = 0; f < 4; f++) mma_tf32(acc[i][f], af[i], bf2[f]);
        }
        __syncthreads();
        if (kb + 3 < 48) { QKV_STAGE_LOAD(st, (kb + 3) * 16); CP_COMMIT(); }
        st++; if (st == 3) st = 0;
    }

    // epilogue: (+bias)*oscale, tf32, head layout [bh][t][hd]
#pragma unroll
    for (int i = 0; i < 4; i++)
#pragma unroll
        for (int f = 0; f < 4; f++) {
            int col = col0 + wn + 8 * f + 2 * q4;
            float b0 = bias[col], b1 = bias[col + 1];
            int hh = col >> 6, hd = col & 63;
#pragma unroll
            for (int half = 0; half < 2; half++) {
                int row = row0 + wm + 16 * i + g + 8 * half;
                int bb = row >> 10, tt = row & 1023;
                uint2 u;
                u.x = f2tf((acc[i][f][2 * half + 0] + b0) * oscale);
                u.y = f2tf((acc[i][f][2 * half + 1] + b1) * oscale);
                *(uint2*)(out + ((size_t)(bb * H_ + hh) * T_ + tt) * HD_ + hd) = u;
            }
        }
}

// ============================================================
// Flash attention (R6 structure), static softmax (no online max).
// S_log2 = qk*C (q pre-scaled) + ga1'*rb + mask' ; P = exp2(S_log2).
// ============================================================
#define ATT_STAGE 8576
__global__ __launch_bounds__(256, 2)
void attn_kernel(const float* __restrict__ rel_bias)
{
    extern __shared__ float smf[];
    uint32_t* Pp = (uint32_t*)(smf + 2 * ATT_STAGE);   // [128][36]
    float*    Ms = smf + 2 * ATT_STAGE + 4608;         // [1024] pre-scaled mask

    const int tid  = threadIdx.x;
    const int w    = tid >> 5;
    const int lane = tid & 31;
    const int g    = lane >> 2;
    const int q4   = lane & 3;
    const int qb   = 16 * w;
    const int q0   = blockIdx.x * 128;
    const int bh   = blockIdx.y;
    const int b    = bh / H_, h = bh % H_;

    const uint32_t* qptr = g_q + (size_t)bh * T_ * HD_;
    const uint32_t* kptr = g_k + (size_t)bh * T_ * HD_;
    const uint32_t* vptr = g_v + (size_t)bh * T_ * HD_;

    const int r0 = qb + g;
    const int r1 = qb + g + 8;

#define ATT_STAGE_LOAD(s, k0) do {                                             \
    uint32_t* Ks_ = (uint32_t*)(smf + (s) * ATT_STAGE);                        \
    uint32_t* Vs_ = Ks_ + 2176;                                                \
    float*    RB_ = smf + (s) * ATT_STAGE + 4352;                              \
    _Pragma("unroll")                                                          \
    for (int i = 0; i < 2; i++) {                                              \
        int idx = tid + i * 256;                                               \
        int kk = idx >> 4, d4 = (idx & 15) * 4;                                \
        cp16(saddr(&Ks_[kk * 68 + d4]), kptr + (size_t)((k0) + kk) * HD_ + d4);\
        cp16(saddr(&Vs_[kk * 68 + d4]), vptr + (size_t)((k0) + kk) * HD_ + d4);\
    }                                                                          \
    const float* rbp_ = rel_bias + ((size_t)bh * T_ + (k0)) * T_ + q0;         \
    _Pragma("unroll")                                                          \
    for (int i = 0; i < 4; i++) {                                              \
        int idx = tid + i * 256;                                               \
        int kk = idx >> 5, qq = (idx & 31) * 4;                                \
        cp16(saddr(&RB_[kk * 132 + qq]), rbp_ + (size_t)kk * T_ + qq);         \
    } } while (0)

    ATT_STAGE_LOAD(0, 0);
    cp16(saddr(&Ms[tid * 4]), g_msk + (size_t)b * T_ + tid * 4);
    CP_COMMIT();
    ATT_STAGE_LOAD(1, 32);
    CP_COMMIT();

    uint32_t qf[8][4];
    {
        const uint32_t* qa = qptr + (size_t)(q0 + r0) * HD_;
        const uint32_t* qc = qptr + (size_t)(q0 + r1) * HD_;
#pragma unroll
        for (int s = 0; s < 8; s++) {
            qf[s][0] = qa[q4 + 8 * s];
            qf[s][1] = qc[q4 + 8 * s];
            qf[s][2] = qa[q4 + 4 + 8 * s];
            qf[s][3] = qc[q4 + 4 + 8 * s];
        }
    }
    const float ga0  = g_ga1[(size_t)bh * T_ + q0 + r0];
    const float ga1v = g_ga1[(size_t)bh * T_ + q0 + r1];

    float l0 = 0.f, l1 = 0.f;   // per-thread partial row sums
    float oacc[8][4];
#pragma unroll
    for (int f = 0; f < 8; f++)
#pragma unroll
        for (int e = 0; e < 4; e++) oacc[f][e] = 0.f;

    for (int kt = 0; kt < 32; kt++) {
        if (kt + 1 < 32) CP_WAIT1(); else CP_WAIT0();
        __syncthreads();
        const int cur = kt & 1;
        const uint32_t* Ks = (const uint32_t*)(smf + cur * ATT_STAGE);
        const uint32_t* Vs = Ks + 2176;
        const float*    RB = smf + cur * ATT_STAGE + 4352;
        const int k0 = kt * 32;

        // ---- S_log2 = ga'*rb + mask' (init) + C*qk (mma, q pre-scaled) ----
        float sacc[4][4];
#pragma unroll
        for (int f = 0; f < 4; f++) {
            int c0 = 8 * f + 2 * q4;
            sacc[f][0] = fmaf(ga0,  RB[c0 * 132 + r0],       Ms[k0 + c0]);
            sacc[f][1] = fmaf(ga0,  RB[(c0 + 1) * 132 + r0], Ms[k0 + c0 + 1]);
            sacc[f][2] = fmaf(ga1v, RB[c0 * 132 + r1],       Ms[k0 + c0]);
            sacc[f][3] = fmaf(ga1v, RB[(c0 + 1) * 132 + r1], Ms[k0 + c0 + 1]);
        }
#pragma unroll
        for (int s = 0; s < 8; s++) {
            uint32_t bf[4][2];
#pragma unroll
            for (int f = 0; f < 4; f++) {
                bf[f][0] = Ks[(8 * f + g) * 68 + q4 + 8 * s];
                bf[f][1] = Ks[(8 * f + g) * 68 + q4 + 4 + 8 * s];
            }
#pragma unroll
            for (int f = 0; f < 4; f++) mma_tf32(sacc[f], qf[s], bf[f]);
        }

        // ---- static softmax: P = exp2(S); accumulate partial l ----
#pragma unroll
        for (int f = 0; f < 4; f++) {
            sacc[f][0] = exp2f(sacc[f][0]);
            sacc[f][1] = exp2f(sacc[f][1]);
            sacc[f][2] = exp2f(sacc[f][2]);
            sacc[f][3] = exp2f(sacc[f][3]);
            l0 += sacc[f][0] + sacc[f][1];
            l1 += sacc[f][2] + sacc[f][3];
        }

        // ---- stage P (tf32) ----
#pragma unroll
        for (int f = 0; f < 4; f++) {
            int c0 = 8 * f + 2 * q4;
            Pp[r0 * 36 + c0]     = f2tf(sacc[f][0]);
            Pp[r0 * 36 + c0 + 1] = f2tf(sacc[f][1]);
            Pp[r1 * 36 + c0]     = f2tf(sacc[f][2]);
            Pp[r1 * 36 + c0 + 1] = f2tf(sacc[f][3]);
        }
        __syncwarp();

        // ---- O += P @ V ----
#pragma unroll
        for (int s = 0; s < 4; s++) {
            uint32_t pa[4];
            pa[0] = Pp[r0 * 36 + q4 + 8 * s];
            pa[1] = Pp[r1 * 36 + q4 + 8 * s];
            pa[2] = Pp[r0 * 36 + q4 + 4 + 8 * s];
            pa[3] = Pp[r1 * 36 + q4 + 4 + 8 * s];
#pragma unroll
            for (int f = 0; f < 8; f++) {
                uint32_t vb[2];
                vb[0] = Vs[(8 * s + q4) * 68 + 8 * f + g];
                vb[1] = Vs[(8 * s + q4 + 4) * 68 + 8 * f + g];
                mma_tf32(oacc[f], pa, vb);
            }
        }
        __syncthreads();
        if (kt + 2 < 32) { ATT_STAGE_LOAD(cur, (kt + 2) * 32); CP_COMMIT(); }
    }

    // ---- reduce l across quad (cols live in q4 lanes), finalize ----
    l0 += __shfl_xor_sync(0xffffffffu, l0, 1);
    l0 += __shfl_xor_sync(0xffffffffu, l0, 2);
    l1 += __shfl_xor_sync(0xffffffffu, l1, 1);
    l1 += __shfl_xor_sync(0xffffffffu, l1, 2);
    float inv0 = 1.f / l0, inv1 = 1.f / l1;
#pragma unroll
    for (int f = 0; f < 8; f++) {
        int c = 8 * f + 2 * q4;
        size_t i0 = ((size_t)b * T_ + q0 + r0) * D_ + h * HD_ + c;
        size_t i1 = ((size_t)b * T_ + q0 + r1) * D_ + h * HD_ + c;
        float v00 = oacc[f][0] * inv0, v01 = oacc[f][1] * inv0;
        float v10 = oacc[f][2] * inv1, v11 = oacc[f][3] * inv1;
        __nv_bfloat16 h00,l00,h01,l01,h10,l10,h11,l11;
        bfsplit(v00,h00,l00); bfsplit(v01,h01,l01);
        bfsplit(v10,h10,l10); bfsplit(v11,h11,l11);
        *(__nv_bfloat162*)(g_oh + i0) = {h00, h01};
        *(__nv_bfloat162*)(g_ol + i0) = {l00, l01};
        *(__nv_bfloat162*)(g_oh + i1) = {h10, h11};
        *(__nv_bfloat162*)(g_ol + i1) = {l10, l11};
    }
}

// ============================================================
// O-proj GEMM, bf16 3-term with ldmatrix (proven R6 kernel).
// ============================================================
#define OB_STAGE 40960
__global__ __launch_bounds__(256, 2)
void gemm_o3(const __nv_bfloat16* __restrict__ Ah, const __nv_bfloat16* __restrict__ Al,
             const __nv_bfloat16* __restrict__ Bh, const __nv_bfloat16* __restrict__ Bl,
             const float* __restrict__ bias, float* __restrict__ out)
{
    extern __shared__ char smo[];
    const int tid = threadIdx.x;
    const int w = tid >> 5, lane = tid & 31, g = lane >> 2, q4 = lane & 3;
    const int wm = (w & 1) * 64, wn = (w >> 1) * 32;
    const int row0 = blockIdx.x * 128, col0 = blockIdx.y * 128;

    float acc[4][4][4];
#pragma unroll
    for (int i = 0; i < 4; i++)
#pragma unroll
        for (int f = 0; f < 4; f++)
#pragma unroll
            for (int e = 0; e < 4; e++) acc[i][f][e] = 0.f;

    const int lrow = lane & 15;
    const int lchk = (lane >> 4) * 16;

#define O3_STAGE_LOAD(s, k0) do {                                              \
    char* base_ = smo + (s) * OB_STAGE;                                        \
    _Pragma("unroll")                                                          \
    for (int i = 0; i < 2; i++) {                                              \
        int idx = tid + i * 256;                                               \
        int r = idx >> 2, ch = idx & 3;                                        \
        uint32_t so = saddr(base_ + r * 80 + ch * 16);                         \
        cp16(so,         Ah + (size_t)(row0 + r) * D_ + (k0) + ch * 8);        \
        cp16(so + 10240, Al + (size_t)(row0 + r) * D_ + (k0) + ch * 8);        \
        cp16(so + 20480, Bh + (size_t)(col0 + r) * D_ + (k0) + ch * 8);        \
        cp16(so + 30720, Bl + (size_t)(col0 + r) * D_ + (k0) + ch * 8);        \
    } } while (0)

    O3_STAGE_LOAD(0, 0);  CP_COMMIT();
    O3_STAGE_LOAD(1, 32); CP_COMMIT();

    for (int kb = 0; kb < 24; kb++) {
        if (kb + 1 < 24) CP_WAIT1(); else CP_WAIT0();
        __syncthreads();
        char* base = smo + (kb & 1) * OB_STAGE;
#pragma unroll
        for (int ks = 0; ks < 2; ks++) {
            uint32_t ah[4][4], al[4][4];
#pragma unroll
            for (int i = 0; i < 4; i++) {
                uint32_t a = saddr(base + (wm + 16 * i + lrow) * 80 + ks * 32 + lchk);
                LDSM_X4(ah[i], a);
                LDSM_X4(al[i], a + 10240);
            }
            uint32_t bh4[2][4], bl4[2][4];
#pragma unroll
            for (int j = 0; j < 2; j++) {
                uint32_t a = saddr(base + 20480 + (wn + 16 * j + lrow) * 80 + ks * 32 + lchk);
                LDSM_X4(bh4[j], a);
                LDSM_X4(bl4[j], a + 10240);
            }
#pragma unroll
            for (int i = 0; i < 4; i++)
#pragma unroll
                for (int f = 0; f < 4; f++) {
                    uint32_t bhf[2] = { bh4[f >> 1][f & 1], bh4[f >> 1][(f & 1) + 2] };
                    uint32_t blf[2] = { bl4[f >> 1][f & 1], bl4[f >> 1][(f & 1) + 2] };
                    mma_bf16(acc[i][f], ah[i], bhf);
                    mma_bf16(acc[i][f], ah[i], blf);
                    mma_bf16(acc[i][f], al[i], bhf);
                }
        }
        __syncthreads();
        if (kb + 2 < 24) { O3_STAGE_LOAD(kb & 1, (kb + 2) * 32); CP_COMMIT(); }
    }

#pragma unroll
    for (int i = 0; i < 4; i++)
#pragma unroll
        for (int f = 0; f < 4; f++) {
            int col = col0 + wn + 8 * f + 2 * q4;
            float b0 = bias[col], b1 = bias[col + 1];
#pragma unroll
            for (int half = 0; half < 2; half++) {
                int row = row0 + wm + 16 * i + g + 8 * half;
                float2 v;
                v.x = acc[i][f][2 * half + 0] + b0;
                v.y = acc[i][f][2 * half + 1] + b1;
                *(float2*)(out + (size_t)row * D_ + col) = v;
            }
        }
}

// ============================================================
extern "C" void kernel_launch(void* const* d_in, const int* in_sizes, int n_in,
                              void* d_out, int out_size)
{
    const float* x         = (const float*)d_in[0];
    const float* attn_mask = (const float*)d_in[1];
    const float* rel_bias  = (const float*)d_in[2];
    const float* Wq = (const float*)d_in[3];
    const float* bq = (const float*)d_in[4];
    const float* Wk = (const float*)d_in[5];
    const float* bk = (const float*)d_in[6];
    const float* Wv = (const float*)d_in[7];
    const float* bv = (const float*)d_in[8];
    const float* Wo = (const float*)d_in[9];
    const float* bo = (const float*)d_in[10];
    const float* Wg = (const float*)d_in[11];
    const float* bg = (const float*)d_in[12];
    const float* grep_a = (const float*)d_in[13];
    float* out = (float*)d_out;

    uint32_t *xhi, *wqh, *wkh, *wvh, *q, *k, *v;
    __nv_bfloat16 *woth, *wotl, *oh, *ol;
    float *ga1;
    cudaGetSymbolAddress((void**)&xhi,  g_xhi);
    cudaGetSymbolAddress((void**)&wqh,  g_wqh);
    cudaGetSymbolAddress((void**)&wkh,  g_wkh);
    cudaGetSymbolAddress((void**)&wvh,  g_wvh);
    cudaGetSymbolAddress((void**)&woth, g_woth);
    cudaGetSymbolAddress((void**)&wotl, g_wotl);
    cudaGetSymbolAddress((void**)&q,    g_q);
    cudaGetSymbolAddress((void**)&k,    g_k);
    cudaGetSymbolAddress((void**)&v,    g_v);
    cudaGetSymbolAddress((void**)&oh,   g_oh);
    cudaGetSymbolAddress((void**)&ol,   g_ol);
    cudaGetSymbolAddress((void**)&ga1,  g_ga1);

    cudaFuncSetAttribute(gemm_qkv,    cudaFuncAttributeMaxDynamicSharedMemorySize, QKV_STAGE * 3 * 4);
    cudaFuncSetAttribute(attn_kernel, cudaFuncAttributeMaxDynamicSharedMemorySize, 91136);
    cudaFuncSetAttribute(gemm_o3,     cudaFuncAttributeMaxDynamicSharedMemorySize, OB_STAGE * 2);

    const int nx4 = N_ * D_ / 4;
    const int nw4 = D_ * D_ / 4;
    conv_x<<<(nx4 + 255) / 256, 256>>>((const float4*)x, (uint4*)xhi, nx4, Wg, bg);    // 0
    conv_w3<<<dim3((nw4 + 255) / 256, 1, 3), 256>>>(                                    // 1
        (const float4*)Wq, (const float4*)Wk, (const float4*)Wv,
        (uint4*)wqh, (uint4*)wkh, (uint4*)wvh, nw4);
    conv_woT<<<dim3(24, 24), dim3(32, 32)>>>(Wo, woth, wotl);                           // 2
    gates_kernel<<<BH_ * T_ / 8, 256>>>(x, grep_a, attn_mask, ga1);                     // 3
    gemm_qkv<<<dim3(64, 6, 3), 256, QKV_STAGE * 3 * 4>>>(                               // 4
        xhi, wqh, wkh, wvh, bq, bk, bv, q, k, v);
    attn_kernel<<<dim3(T_ / 128, BH_), 256, 91136>>>(rel_bias);                         // 5
    gemm_o3<<<dim3(64, 6), 256, OB_STAGE * 2>>>(oh, ol, woth, wotl, bo, out);           // 6
}

// round 10
// speedup vs baseline: 1.2778x; 1.0867x over previous
#include <cuda_runtime.h>
#include <cuda_bf16.h>
#include <math.h>
#include <stdint.h>

#define B_  8
#define T_  1024
#define D_  768
#define H_  12
#define HD_ 64
#define BH_ (B_*H_)   /* 96 */
#define N_  (B_*T_)   /* 8192 */
#define WSZ_ ((size_t)D_*D_)
#define C_SM  (0.125f * 1.44269504088896340736f)   /* 0.125*log2(e) */
#define K8C   (1.44269504088896340736f)            /* log2(e) */

// ---- scratch (static device globals; no allocation) ----
__device__ uint32_t g_xhi[N_*D_];          // x tf32
__device__ uint32_t g_wqh[D_*D_];          // Wq tf32
__device__ uint32_t g_wkh[D_*D_];
__device__ uint32_t g_wvh[D_*D_];
__device__ __nv_bfloat16 g_woth[D_*D_];    // Wo^T bf16 hi [n][k]
__device__ __nv_bfloat16 g_wotl[D_*D_];    // Wo^T bf16 lo
__device__ uint32_t g_q[BH_*T_*HD_];       // tf32 (pre-scaled by C_SM), head layout
__device__ uint32_t g_k[BH_*T_*HD_];       // tf32, head layout
__device__ uint32_t g_v[BH_*T_*HD_];       // tf32, head layout
__device__ __nv_bfloat16 g_oh[N_*D_];      // attn out hi bf16, row-major
__device__ __nv_bfloat16 g_ol[N_*D_];      // attn out lo
__device__ float    g_ga1[BH_*T_];         // log2e * ga1
__device__ float    g_msk[N_];             // log2e * attn_mask  [b][t]
__device__ float    g_wg2[HD_*2];
__device__ float    g_bg2[2];

// ---- helpers ----
__device__ __forceinline__ uint32_t f2tf(float f) {
    uint32_t u;
    asm("cvt.rna.tf32.f32 %0, %1;" : "=r"(u) : "f"(f));
    return u;
}
__device__ __forceinline__ float ex2(float x) {
    float r;
    asm("ex2.approx.f32 %0, %1;" : "=f"(r) : "f"(x));
    return r;
}
__device__ __forceinline__ void mma_tf32(float* d, const uint32_t* a, const uint32_t* b) {
    asm volatile(
        "mma.sync.aligned.m16n8k8.row.col.f32.tf32.tf32.f32 "
        "{%0,%1,%2,%3}, {%4,%5,%6,%7}, {%8,%9}, {%0,%1,%2,%3};\n"
        : "+f"(d[0]), "+f"(d[1]), "+f"(d[2]), "+f"(d[3])
        : "r"(a[0]), "r"(a[1]), "r"(a[2]), "r"(a[3]), "r"(b[0]), "r"(b[1]));
}
__device__ __forceinline__ void mma_bf16(float* d, const uint32_t* a, const uint32_t* b) {
    asm volatile(
        "mma.sync.aligned.m16n8k16.row.col.f32.bf16.bf16.f32 "
        "{%0,%1,%2,%3}, {%4,%5,%6,%7}, {%8,%9}, {%0,%1,%2,%3};\n"
        : "+f"(d[0]), "+f"(d[1]), "+f"(d[2]), "+f"(d[3])
        : "r"(a[0]), "r"(a[1]), "r"(a[2]), "r"(a[3]), "r"(b[0]), "r"(b[1]));
}
#define LDSM_X4(r, a) \
    asm volatile("ldmatrix.sync.aligned.m8n8.x4.shared.b16 {%0,%1,%2,%3}, [%4];" \
        : "=r"((r)[0]), "=r"((r)[1]), "=r"((r)[2]), "=r"((r)[3]) : "r"(a))

__device__ __forceinline__ uint32_t saddr(const void* p) {
    return (uint32_t)__cvta_generic_to_shared(p);
}
__device__ __forceinline__ void cp16(uint32_t s, const void* g) {
    asm volatile("cp.async.cg.shared.global [%0], [%1], 16;\n" :: "r"(s), "l"(g));
}
#define CP_COMMIT() asm volatile("cp.async.commit_group;\n")
#define CP_WAIT2()  asm volatile("cp.async.wait_group 2;\n")
#define CP_WAIT1()  asm volatile("cp.async.wait_group 1;\n")
#define CP_WAIT0()  asm volatile("cp.async.wait_group 0;\n")

__device__ __forceinline__ void bfsplit(float f, __nv_bfloat16& h, __nv_bfloat16& l) {
    h = __float2bfloat16(f);
    l = __float2bfloat16(f - __bfloat162float(h));
}

// ============================================================
// conv_all: one kernel for all preconversion.
//  blocks [0,6144)      : x -> tf32
//  blocks [6144,7872)   : Wq/Wk/Wv -> tf32 (576 blocks each)
//  blocks [7872,8448)   : Wo -> Wo^T bf16 hi/lo (24x24 tiles)
//  block 0 threads<64   : Wg row-sums
// ============================================================
#define NXB 6144
#define NWB 576
__global__ __launch_bounds__(256)
void conv_all(const float4* __restrict__ x,
              const float4* __restrict__ Wq, const float4* __restrict__ Wk,
              const float4* __restrict__ Wv, const float*  __restrict__ Wo,
              const float* __restrict__ Wg, const float* __restrict__ bg,
              uint4* __restrict__ xhi, uint4* __restrict__ wqh,
              uint4* __restrict__ wkh, uint4* __restrict__ wvh,
              __nv_bfloat16* __restrict__ woth, __nv_bfloat16* __restrict__ wotl)
{
    __shared__ float tile[32][33];
    const int bid = blockIdx.x, tid = threadIdx.x;

    if (bid == 0 && tid < 64) {
        int d = tid;
        const float* wg = Wg + d * 8;
        g_wg2[d * 2 + 0] = wg[0] + wg[1] + wg[2] + wg[3];
        g_wg2[d * 2 + 1] = wg[4] + wg[5] + wg[6] + wg[7];
        if (d == 0) {
            g_bg2[0] = bg[0] + bg[1] + bg[2] + bg[3];
            g_bg2[1] = bg[4] + bg[5] + bg[6] + bg[7];
        }
    }

    if (bid < NXB) {
        int i = bid * 256 + tid;
        float4 v = x[i];
        uint4 h;
        h.x = f2tf(v.x); h.y = f2tf(v.y); h.z = f2tf(v.z); h.w = f2tf(v.w);
        xhi[i] = h;
    } else if (bid < NXB + 3 * NWB) {
        int r = bid - NXB;
        int z = r / NWB;
        int i = (r % NWB) * 256 + tid;
        const float4* in = (z == 0) ? Wq : (z == 1) ? Wk : Wv;
        uint4* out = (z == 0) ? wqh : (z == 1) ? wkh : wvh;
        float4 v = in[i];
        uint4 h;
        h.x = f2tf(v.x); h.y = f2tf(v.y); h.z = f2tf(v.z); h.w = f2tf(v.w);
        out[i] = h;
    } else {
        int bx = bid - (NXB + 3 * NWB);
        int n0 = (bx % 24) * 32, k0 = (bx / 24) * 32;
        int tx = tid & 31, ty0 = tid >> 5;
#pragma unroll
        for (int j = 0; j < 4; j++)
            tile[ty0 + 8 * j][tx] = Wo[(size_t)(k0 + ty0 + 8 * j) * D_ + n0 + tx];
        __syncthreads();
#pragma unroll
        for (int j = 0; j < 4; j++) {
            int ty = ty0 + 8 * j;
            float f = tile[tx][ty];
            __nv_bfloat16 h, l;
            bfsplit(f, h, l);
            size_t o = (size_t)(n0 + ty) * D_ + k0 + tx;
            woth[o] = h; wotl[o] = l;
        }
    }
}

// ============================================================
// Gates: emits log2e*ga1 ; also pre-scales the mask.
// ============================================================
__global__ __launch_bounds__(256)
void gates_kernel(const float* __restrict__ x, const float* __restrict__ grep_a,
                  const float* __restrict__ attn_mask, float* __restrict__ ga1)
{
    int gidx = blockIdx.x * 256 + threadIdx.x;
    if (gidx < N_) g_msk[gidx] = K8C * attn_mask[gidx];

    int w    = blockIdx.x * 8 + (threadIdx.x >> 5);
    int lane = threadIdx.x & 31;
    int bh = w >> 10, t = w & 1023;
    int b = bh / H_, h = bh % H_;
    const float* xp = x + ((size_t)b * T_ + t) * D_ + h * HD_;

    float s0 = 0.f, s1 = 0.f;
#pragma unroll
    for (int d = lane; d < HD_; d += 32) {
        float xv = xp[d];
        s0 += xv * g_wg2[d * 2 + 0];
        s1 += xv * g_wg2[d * 2 + 1];
    }
#pragma unroll
    for (int off = 16; off > 0; off >>= 1) {
        s0 += __shfl_xor_sync(0xffffffffu, s0, off);
        s1 += __shfl_xor_sync(0xffffffffu, s1, off);
    }
    if (lane == 0) {
        s0 += g_bg2[0];
        s1 += g_bg2[1];
        float ga = 1.f / (1.f + expf(-s0));
        float gb = 1.f / (1.f + expf(-s1));
        ga1[w] = K8C * (ga * (gb * grep_a[h] - 1.f) + 2.f);
    }
}

// ============================================================
// Merged QKV GEMM (tf32, 1-term): out_z = tf32(x@W_z + b_z), head layout.
// Q (z==0) pre-scaled by C_SM. BM=128 BN=128 BK=16, 3-stage ring.
// ============================================================
#define QKV_STAGE 4736
__global__ __launch_bounds__(256, 2)
void gemm_qkv(const uint32_t* __restrict__ A,
              const uint32_t* __restrict__ W0, const uint32_t* __restrict__ W1,
              const uint32_t* __restrict__ W2,
              const float* __restrict__ bb0, const float* __restrict__ bb1,
              const float* __restrict__ bb2,
              uint32_t* __restrict__ o0, uint32_t* __restrict__ o1,
              uint32_t* __restrict__ o2)
{
    extern __shared__ uint32_t sm[];
    const int z = blockIdx.z;
    const uint32_t* W = (z == 0) ? W0 : (z == 1) ? W1 : W2;
    const float* bias = (z == 0) ? bb0 : (z == 1) ? bb1 : bb2;
    uint32_t* out     = (z == 0) ? o0 : (z == 1) ? o1 : o2;
    const float oscale = (z == 0) ? C_SM : 1.f;

    const int tid = threadIdx.x;
    const int w = tid >> 5, lane = tid & 31, g = lane >> 2, q4 = lane & 3;
    const int wm = (w & 1) * 64, wn = (w >> 1) * 32;
    const int row0 = blockIdx.x * 128, col0 = blockIdx.y * 128;

    float acc[4][4][4];
#pragma unroll
    for (int i = 0; i < 4; i++)
#pragma unroll
        for (int f = 0; f < 4; f++)
#pragma unroll
            for (int e = 0; e < 4; e++) acc[i][f][e] = 0.f;

#define QKV_STAGE_LOAD(s, k0) do {                                             \
    uint32_t* As_ = sm + (s) * QKV_STAGE;                                      \
    uint32_t* Bs_ = As_ + 2560;                                                \
    _Pragma("unroll")                                                          \
    for (int i = 0; i < 2; i++) {                                              \
        int idx = tid + i * 256;                                               \
        int m = idx >> 2, kc = (idx & 3) * 4;                                  \
        cp16(saddr(&As_[m * 20 + kc]), A + (size_t)(row0 + m) * D_ + (k0) + kc); \
        int kk = idx >> 5, n4 = (idx & 31) * 4;                                \
        cp16(saddr(&Bs_[kk * 136 + n4]), W + (size_t)((k0) + kk) * D_ + col0 + n4); \
    } } while (0)

    QKV_STAGE_LOAD(0, 0);  CP_COMMIT();
    QKV_STAGE_LOAD(1, 16); CP_COMMIT();
    QKV_STAGE_LOAD(2, 32); CP_COMMIT();

    int st = 0;
    for (int kb = 0; kb < 48; kb++) {
        if (kb + 2 < 48) CP_WAIT2(); else CP_WAIT0();
        __syncthreads();
        const uint32_t* As = sm + st * QKV_STAGE;
        const uint32_t* Bs = As + 2560;
#pragma unroll
        for (int s = 0; s < 2; s++) {
            int kc = 8 * s + q4;
            uint32_t af[4][4], bf2[4][2];
#pragma unroll
            for (int i = 0; i < 4; i++) {
                int r = wm + 16 * i + g;
                af[i][0] = As[r * 20 + kc];       af[i][1] = As[(r + 8) * 20 + kc];
                af[i][2] = As[r * 20 + kc + 4];   af[i][3] = As[(r + 8) * 20 + kc + 4];
            }
#pragma unroll
            for (int f = 0; f < 4; f++) {
                int n = wn + 8 * f + g;
                bf2[f][0] = Bs[kc * 136 + n];
                bf2[f][1] = Bs[(kc + 4) * 136 + n];
            }
#pragma unroll
            for (int i = 0; i < 4; i++)
#pragma unroll
                for (int f = 0; f < 4; f++) mma_tf32(acc[i][f], af[i], bf2[f]);
        }
        __syncthreads();
        if (kb + 3 < 48) { QKV_STAGE_LOAD(st, (kb + 3) * 16); CP_COMMIT(); }
        st++; if (st == 3) st = 0;
    }

    // epilogue: (+bias)*oscale, tf32, head layout [bh][t][hd]
#pragma unroll
    for (int i = 0; i < 4; i++)
#pragma unroll
        for (int f = 0; f < 4; f++) {
            int col = col0 + wn + 8 * f + 2 * q4;
            float b0 = bias[col], b1 = bias[col + 1];
            int hh = col >> 6, hd = col & 63;
#pragma unroll
            for (int half = 0; half < 2; half++) {
                int row = row0 + wm + 16 * i + g + 8 * half;
                int bb = row >> 10, tt = row & 1023;
                uint2 u;
                u.x = f2tf((acc[i][f][2 * half + 0] + b0) * oscale);
                u.y = f2tf((acc[i][f][2 * half + 1] + b1) * oscale);
                *(uint2*)(out + ((size_t)(bb * H_ + hh) * T_ + tt) * HD_ + hd) = u;
            }
        }
}

// ============================================================
// Flash attention, static softmax, conflict-free V (stride 72).
// stage (words): Ks 32x68=2176 + Vs 32x72=2304 + RB 32x132=4224 = 8704
//  x2 stages = 17408 ; Pp 128x36 = 4608 ; Ms 1024 => 23040 w = 92160 B
// ============================================================
#define ATT_STAGE 8704
__global__ __launch_bounds__(256, 2)
void attn_kernel(const float* __restrict__ rel_bias)
{
    extern __shared__ float smf[];
    uint32_t* Pp = (uint32_t*)(smf + 2 * ATT_STAGE);   // [128][36]
    float*    Ms = smf + 2 * ATT_STAGE + 4608;         // [1024] pre-scaled mask

    const int tid  = threadIdx.x;
    const int w    = tid >> 5;
    const int lane = tid & 31;
    const int g    = lane >> 2;
    const int q4   = lane & 3;
    const int qb   = 16 * w;
    const int q0   = blockIdx.x * 128;
    const int bh   = blockIdx.y;
    const int b    = bh / H_, h = bh % H_;

    const uint32_t* qptr = g_q + (size_t)bh * T_ * HD_;
    const uint32_t* kptr = g_k + (size_t)bh * T_ * HD_;
    const uint32_t* vptr = g_v + (size_t)bh * T_ * HD_;

    const int r0 = qb + g;
    const int r1 = qb + g + 8;

#define ATT_STAGE_LOAD(s, k0) do {                                             \
    uint32_t* Ks_ = (uint32_t*)(smf + (s) * ATT_STAGE);                        \
    uint32_t* Vs_ = Ks_ + 2176;                                                \
    float*    RB_ = smf + (s) * ATT_STAGE + 4480;                              \
    _Pragma("unroll")                                                          \
    for (int i = 0; i < 2; i++) {                                              \
        int idx = tid + i * 256;                                               \
        int kk = idx >> 4, d4 = (idx & 15) * 4;                                \
        cp16(saddr(&Ks_[kk * 68 + d4]), kptr + (size_t)((k0) + kk) * HD_ + d4);\
        cp16(saddr(&Vs_[kk * 72 + d4]), vptr + (size_t)((k0) + kk) * HD_ + d4);\
    }                                                                          \
    const float* rbp_ = rel_bias + ((size_t)bh * T_ + (k0)) * T_ + q0;         \
    _Pragma("unroll")                                                          \
    for (int i = 0; i < 4; i++) {                                              \
        int idx = tid + i * 256;                                               \
        int kk = idx >> 5, qq = (idx & 31) * 4;                                \
        cp16(saddr(&RB_[kk * 132 + qq]), rbp_ + (size_t)kk * T_ + qq);         \
    } } while (0)

    ATT_STAGE_LOAD(0, 0);
    cp16(saddr(&Ms[tid * 4]), g_msk + (size_t)b * T_ + tid * 4);
    CP_COMMIT();
    ATT_STAGE_LOAD(1, 32);
    CP_COMMIT();

    uint32_t qf[8][4];
    {
        const uint32_t* qa = qptr + (size_t)(q0 + r0) * HD_;
        const uint32_t* qc = qptr + (size_t)(q0 + r1) * HD_;
#pragma unroll
        for (int s = 0; s < 8; s++) {
            qf[s][0] = qa[q4 + 8 * s];
            qf[s][1] = qc[q4 + 8 * s];
            qf[s][2] = qa[q4 + 4 + 8 * s];
            qf[s][3] = qc[q4 + 4 + 8 * s];
        }
    }
    const float ga0  = g_ga1[(size_t)bh * T_ + q0 + r0];
    const float ga1v = g_ga1[(size_t)bh * T_ + q0 + r1];

    float l0 = 0.f, l1 = 0.f;
    float oacc[8][4];
#pragma unroll
    for (int f = 0; f < 8; f++)
#pragma unroll
        for (int e = 0; e < 4; e++) oacc[f][e] = 0.f;

    for (int kt = 0; kt < 32; kt++) {
        if (kt + 1 < 32) CP_WAIT1(); else CP_WAIT0();
        __syncthreads();
        const int cur = kt & 1;
        const uint32_t* Ks = (const uint32_t*)(smf + cur * ATT_STAGE);
        const uint32_t* Vs = Ks + 2176;
        const float*    RB = smf + cur * ATT_STAGE + 4480;
        const int k0 = kt * 32;

        // ---- S_log2 = ga'*rb + mask' (init) + C*qk (mma, q pre-scaled) ----
        float sacc[4][4];
#pragma unroll
        for (int f = 0; f < 4; f++) {
            int c0 = 8 * f + 2 * q4;
            sacc[f][0] = fmaf(ga0,  RB[c0 * 132 + r0],       Ms[k0 + c0]);
            sacc[f][1] = fmaf(ga0,  RB[(c0 + 1) * 132 + r0], Ms[k0 + c0 + 1]);
            sacc[f][2] = fmaf(ga1v, RB[c0 * 132 + r1],       Ms[k0 + c0]);
            sacc[f][3] = fmaf(ga1v, RB[(c0 + 1) * 132 + r1], Ms[k0 + c0 + 1]);
        }
#pragma unroll
        for (int s = 0; s < 8; s++) {
            uint32_t bf[4][2];
#pragma unroll
            for (int f = 0; f < 4; f++) {
                bf[f][0] = Ks[(8 * f + g) * 68 + q4 + 8 * s];
                bf[f][1] = Ks[(8 * f + g) * 68 + q4 + 4 + 8 * s];
            }
#pragma unroll
            for (int f = 0; f < 4; f++) mma_tf32(sacc[f], qf[s], bf[f]);
        }

        // ---- static softmax: P = exp2(S); accumulate partial l ----
#pragma unroll
        for (int f = 0; f < 4; f++) {
            sacc[f][0] = ex2(sacc[f][0]);
            sacc[f][1] = ex2(sacc[f][1]);
            sacc[f][2] = ex2(sacc[f][2]);
            sacc[f][3] = ex2(sacc[f][3]);
            l0 += sacc[f][0] + sacc[f][1];
            l1 += sacc[f][2] + sacc[f][3];
        }

        // ---- stage P (tf32) ----
#pragma unroll
        for (int f = 0; f < 4; f++) {
            int c0 = 8 * f + 2 * q4;
            Pp[r0 * 36 + c0]     = f2tf(sacc[f][0]);
            Pp[r0 * 36 + c0 + 1] = f2tf(sacc[f][1]);
            Pp[r1 * 36 + c0]     = f2tf(sacc[f][2]);
            Pp[r1 * 36 + c0 + 1] = f2tf(sacc[f][3]);
        }
        __syncwarp();

        // ---- O += P @ V (V stride 72: conflict-free) ----
#pragma unroll
        for (int s = 0; s < 4; s++) {
            uint32_t pa[4];
            pa[0] = Pp[r0 * 36 + q4 + 8 * s];
            pa[1] = Pp[r1 * 36 + q4 + 8 * s];
            pa[2] = Pp[r0 * 36 + q4 + 4 + 8 * s];
            pa[3] = Pp[r1 * 36 + q4 + 4 + 8 * s];
#pragma unroll
            for (int f = 0; f < 8; f++) {
                uint32_t vb[2];
                vb[0] = Vs[(8 * s + q4) * 72 + 8 * f + g];
                vb[1] = Vs[(8 * s + q4 + 4) * 72 + 8 * f + g];
                mma_tf32(oacc[f], pa, vb);
            }
        }
        __syncthreads();
        if (kt + 2 < 32) { ATT_STAGE_LOAD(cur, (kt + 2) * 32); CP_COMMIT(); }
    }

    // ---- reduce l across quad, finalize ----
    l0 += __shfl_xor_sync(0xffffffffu, l0, 1);
    l0 += __shfl_xor_sync(0xffffffffu, l0, 2);
    l1 += __shfl_xor_sync(0xffffffffu, l1, 1);
    l1 += __shfl_xor_sync(0xffffffffu, l1, 2);
    float inv0 = 1.f / l0, inv1 = 1.f / l1;
#pragma unroll
    for (int f = 0; f < 8; f++) {
        int c = 8 * f + 2 * q4;
        size_t i0 = ((size_t)b * T_ + q0 + r0) * D_ + h * HD_ + c;
        size_t i1 = ((size_t)b * T_ + q0 + r1) * D_ + h * HD_ + c;
        float v00 = oacc[f][0] * inv0, v01 = oacc[f][1] * inv0;
        float v10 = oacc[f][2] * inv1, v11 = oacc[f][3] * inv1;
        __nv_bfloat16 h00,l00,h01,l01,h10,l10,h11,l11;
        bfsplit(v00,h00,l00); bfsplit(v01,h01,l01);
        bfsplit(v10,h10,l10); bfsplit(v11,h11,l11);
        *(__nv_bfloat162*)(g_oh + i0) = {h00, h01};
        *(__nv_bfloat162*)(g_ol + i0) = {l00, l01};
        *(__nv_bfloat162*)(g_oh + i1) = {h10, h11};
        *(__nv_bfloat162*)(g_ol + i1) = {l10, l11};
    }
}

// ============================================================
// O-proj GEMM, bf16 3-term with ldmatrix (proven kernel).
// ============================================================
#define OB_STAGE 40960
__global__ __launch_bounds__(256, 2)
void gemm_o3(const __nv_bfloat16* __restrict__ Ah, const __nv_bfloat16* __restrict__ Al,
             const __nv_bfloat16* __restrict__ Bh, const __nv_bfloat16* __restrict__ Bl,
             const float* __restrict__ bias, float* __restrict__ out)
{
    extern __shared__ char smo[];
    const int tid = threadIdx.x;
    const int w = tid >> 5, lane = tid & 31, g = lane >> 2, q4 = lane & 3;
    const int wm = (w & 1) * 64, wn = (w >> 1) * 32;
    const int row0 = blockIdx.x * 128, col0 = blockIdx.y * 128;

    float acc[4][4][4];
#pragma unroll
    for (int i = 0; i < 4; i++)
#pragma unroll
        for (int f = 0; f < 4; f++)
#pragma unroll
            for (int e = 0; e < 4; e++) acc[i][f][e] = 0.f;

    const int lrow = lane & 15;
    const int lchk = (lane >> 4) * 16;

#define O3_STAGE_LOAD(s, k0) do {                                              \
    char* base_ = smo + (s) * OB_STAGE;                                        \
    _Pragma("unroll")                                                          \
    for (int i = 0; i < 2; i++) {                                              \
        int idx = tid + i * 256;                                               \
        int r = idx >> 2, ch = idx & 3;                                        \
        uint32_t so = saddr(base_ + r * 80 + ch * 16);                         \
        cp16(so,         Ah + (size_t)(row0 + r) * D_ + (k0) + ch * 8);        \
        cp16(so + 10240, Al + (size_t)(row0 + r) * D_ + (k0) + ch * 8);        \
        cp16(so + 20480, Bh + (size_t)(col0 + r) * D_ + (k0) + ch * 8);        \
        cp16(so + 30720, Bl + (size_t)(col0 + r) * D_ + (k0) + ch * 8);        \
    } } while (0)

    O3_STAGE_LOAD(0, 0);  CP_COMMIT();
    O3_STAGE_LOAD(1, 32); CP_COMMIT();

    for (int kb = 0; kb < 24; kb++) {
        if (kb + 1 < 24) CP_WAIT1(); else CP_WAIT0();
        __syncthreads();
        char* base = smo + (kb & 1) * OB_STAGE;
#pragma unroll
        for (int ks = 0; ks < 2; ks++) {
            uint32_t ah[4][4], al[4][4];
#pragma unroll
            for (int i = 0; i < 4; i++) {
                uint32_t a = saddr(base + (wm + 16 * i + lrow) * 80 + ks * 32 + lchk);
                LDSM_X4(ah[i], a);
                LDSM_X4(al[i], a + 10240);
            }
            uint32_t bh4[2][4], bl4[2][4];
#pragma unroll
            for (int j = 0; j < 2; j++) {
                uint32_t a = saddr(base + 20480 + (wn + 16 * j + lrow) * 80 + ks * 32 + lchk);
                LDSM_X4(bh4[j], a);
                LDSM_X4(bl4[j], a + 10240);
            }
#pragma unroll
            for (int i = 0; i < 4; i++)
#pragma unroll
                for (int f = 0; f < 4; f++) {
                    uint32_t bhf[2] = { bh4[f >> 1][f & 1], bh4[f >> 1][(f & 1) + 2] };
                    uint32_t blf[2] = { bl4[f >> 1][f & 1], bl4[f >> 1][(f & 1) + 2] };
                    mma_bf16(acc[i][f], ah[i], bhf);
                    mma_bf16(acc[i][f], ah[i], blf);
                    mma_bf16(acc[i][f], al[i], bhf);
                }
        }
        __syncthreads();
        if (kb + 2 < 24) { O3_STAGE_LOAD(kb & 1, (kb + 2) * 32); CP_COMMIT(); }
    }

#pragma unroll
    for (int i = 0; i < 4; i++)
#pragma unroll
        for (int f = 0; f < 4; f++) {
            int col = col0 + wn + 8 * f + 2 * q4;
            float b0 = bias[col], b1 = bias[col + 1];
#pragma unroll
            for (int half = 0; half < 2; half++) {
                int row = row0 + wm + 16 * i + g + 8 * half;
                float2 v;
                v.x = acc[i][f][2 * half + 0] + b0;
                v.y = acc[i][f][2 * half + 1] + b1;
                *(float2*)(out + (size_t)row * D_ + col) = v;
            }
        }
}

// ============================================================
extern "C" void kernel_launch(void* const* d_in, const int* in_sizes, int n_in,
                              void* d_out, int out_size)
{
    const float* x         = (const float*)d_in[0];
    const float* attn_mask = (const float*)d_in[1];
    const float* rel_bias  = (const float*)d_in[2];
    const float* Wq = (const float*)d_in[3];
    const float* bq = (const float*)d_in[4];
    const float* Wk = (const float*)d_in[5];
    const float* bk = (const float*)d_in[6];
    const float* Wv = (const float*)d_in[7];
    const float* bv = (const float*)d_in[8];
    const float* Wo = (const float*)d_in[9];
    const float* bo = (const float*)d_in[10];
    const float* Wg = (const float*)d_in[11];
    const float* bg = (const float*)d_in[12];
    const float* grep_a = (const float*)d_in[13];
    float* out = (float*)d_out;

    uint32_t *xhi, *wqh, *wkh, *wvh, *q, *k, *v;
    __nv_bfloat16 *woth, *wotl, *oh, *ol;
    float *ga1;
    cudaGetSymbolAddress((void**)&xhi,  g_xhi);
    cudaGetSymbolAddress((void**)&wqh,  g_wqh);
    cudaGetSymbolAddress((void**)&wkh,  g_wkh);
    cudaGetSymbolAddress((void**)&wvh,  g_wvh);
    cudaGetSymbolAddress((void**)&woth, g_woth);
    cudaGetSymbolAddress((void**)&wotl, g_wotl);
    cudaGetSymbolAddress((void**)&q,    g_q);
    cudaGetSymbolAddress((void**)&k,    g_k);
    cudaGetSymbolAddress((void**)&v,    g_v);
    cudaGetSymbolAddress((void**)&oh,   g_oh);
    cudaGetSymbolAddress((void**)&ol,   g_ol);
    cudaGetSymbolAddress((void**)&ga1,  g_ga1);

    cudaFuncSetAttribute(gemm_qkv,    cudaFuncAttributeMaxDynamicSharedMemorySize, QKV_STAGE * 3 * 4);
    cudaFuncSetAttribute(attn_kernel, cudaFuncAttributeMaxDynamicSharedMemorySize, 92160);
    cudaFuncSetAttribute(gemm_o3,     cudaFuncAttributeMaxDynamicSharedMemorySize, OB_STAGE * 2);

    conv_all<<<NXB + 3 * NWB + NWB, 256>>>(                                            // 0
        (const float4*)x, (const float4*)Wq, (const float4*)Wk, (const float4*)Wv,
        Wo, Wg, bg,
        (uint4*)xhi, (uint4*)wqh, (uint4*)wkh, (uint4*)wvh, woth, wotl);
    gates_kernel<<<BH_ * T_ / 8, 256>>>(x, grep_a, attn_mask, ga1);                     // 1
    gemm_qkv<<<dim3(64, 6, 3), 256, QKV_STAGE * 3 * 4>>>(                               // 2
        xhi, wqh, wkh, wvh, bq, bk, bv, q, k, v);
    attn_kernel<<<dim3(T_ / 128, BH_), 256, 92160>>>(rel_bias);                         // 3
    gemm_o3<<<dim3(64, 6), 256, OB_STAGE * 2>>>(oh, ol, woth, wotl, bo, out);           // 4
}